// round 2
// baseline (speedup 1.0000x reference)
#include <cuda_runtime.h>
#include <cuda_bf16.h>
#include <cstdint>

#define NN 100000
#define NE 1600000
#define FF 128
#define GG 64
#define EPSV 1e-5f

// Output layout (float32): h_emb [NN*FF], flat [GG*FF], edge_index [2*NE],
// edge_weight [NE], batch [NN]
#define OUT_FLAT ((size_t)NN * FF)
#define OUT_EI   (OUT_FLAT + (size_t)GG * FF)
#define OUT_EW   (OUT_EI + (size_t)2 * NE)
#define OUT_B    (OUT_EW + (size_t)NE)

// Scratch (device globals)
__device__ float g_dis[NN];
__device__ int   g_cnt[NN];
__device__ int   g_off[NN + 1];
__device__ int   g_cur[NN];
__device__ int   g_csr_src[NE];
__device__ float g_csr_nrm[NE];
__device__ float g_xw[(size_t)NN * FF];
__device__ float g_h[(size_t)NN * FF];
__device__ int   g_starts[GG + 1];
__device__ float g_sum[GG * FF];
__device__ float g_sq[GG * FF];
__device__ float g_scale[GG * FF];
__device__ float g_shift[GG * FF];

// 1. init degree (self-loop weight) + in-degree counts
__global__ void k_init() {
    int i = blockIdx.x * blockDim.x + threadIdx.x;
    if (i < NN) { g_dis[i] = 1.0f; g_cnt[i] = 0; }
}

// 2. weighted degree + integer in-degree
__global__ void k_deg(const int* __restrict__ ei, const float* __restrict__ ew) {
    int e = blockIdx.x * blockDim.x + threadIdx.x;
    if (e < NE) {
        int d = ei[NE + e];
        atomicAdd(&g_dis[d], ew[e]);
        atomicAdd(&g_cnt[d], 1);
    }
}

// 3. deg -> rsqrt(deg)
__global__ void k_rsqrt() {
    int i = blockIdx.x * blockDim.x + threadIdx.x;
    if (i < NN) g_dis[i] = rsqrtf(g_dis[i]);
}

// 4. exclusive prefix scan of counts -> CSR offsets + cursors (single block)
__global__ void k_prefix() {
    __shared__ int sh[1024];
    int tid = threadIdx.x;
    const int CH = (NN + 1023) / 1024;            // 98
    int i0 = tid * CH, i1 = min(i0 + CH, NN);
    int s = 0;
    for (int i = i0; i < i1; ++i) s += g_cnt[i];
    sh[tid] = s;
    __syncthreads();
    for (int off = 1; off < 1024; off <<= 1) {
        int v = (tid >= off) ? sh[tid - off] : 0;
        __syncthreads();
        sh[tid] += v;
        __syncthreads();
    }
    int base = sh[tid] - s;                        // exclusive
    for (int i = i0; i < i1; ++i) {
        g_off[i] = base; g_cur[i] = base;
        base += g_cnt[i];
    }
    if (tid == 1023) g_off[NN] = NE;
}

// 5. slot-scatter edges into CSR order, with fused norm computation
__global__ void k_csr(const int* __restrict__ ei, const float* __restrict__ ew) {
    int e = blockIdx.x * blockDim.x + threadIdx.x;
    if (e >= NE) return;
    int s = ei[e];
    int d = ei[NE + e];
    float nrm = g_dis[s] * ew[e] * g_dis[d];
    int pos = atomicAdd(&g_cur[d], 1);
    g_csr_src[pos] = s;
    g_csr_nrm[pos] = nrm;
}

// 6. xw = X @ W  — packed fp32x2 FMA, 8 rows x 4 cols per thread
__global__ __launch_bounds__(128) void k_gemm(const float* __restrict__ X,
                                              const float* __restrict__ W) {
    int lane = threadIdx.x;               // 0..31
    int ty = threadIdx.y;                 // 0..3
    int col0 = lane * 4;
    int r0 = blockIdx.x * 32 + ty * 8;
    unsigned long long acc[8][2];
#pragma unroll
    for (int r = 0; r < 8; ++r) { acc[r][0] = 0ull; acc[r][1] = 0ull; }

    for (int k4 = 0; k4 < FF; k4 += 4) {
        float4 a[8];
#pragma unroll
        for (int r = 0; r < 8; ++r)
            a[r] = *(const float4*)(X + (size_t)(r0 + r) * FF + k4);
#pragma unroll
        for (int kk = 0; kk < 4; ++kk) {
            float4 w = *(const float4*)(W + (size_t)(k4 + kk) * FF + col0);
            unsigned long long w01, w23;
            asm("mov.b64 %0,{%1,%2};" : "=l"(w01) : "f"(w.x), "f"(w.y));
            asm("mov.b64 %0,{%1,%2};" : "=l"(w23) : "f"(w.z), "f"(w.w));
#pragma unroll
            for (int r = 0; r < 8; ++r) {
                float as = ((const float*)&a[r])[kk];
                unsigned long long p;
                asm("mov.b64 %0,{%1,%1};" : "=l"(p) : "f"(as));
                asm("fma.rn.f32x2 %0,%1,%2,%0;" : "+l"(acc[r][0]) : "l"(p), "l"(w01));
                asm("fma.rn.f32x2 %0,%1,%2,%0;" : "+l"(acc[r][1]) : "l"(p), "l"(w23));
            }
        }
    }
#pragma unroll
    for (int r = 0; r < 8; ++r) {
        float o0, o1, o2, o3;
        asm("mov.b64 {%0,%1},%2;" : "=f"(o0), "=f"(o1) : "l"(acc[r][0]));
        asm("mov.b64 {%0,%1},%2;" : "=f"(o2), "=f"(o3) : "l"(acc[r][1]));
        *(float4*)(g_xw + (size_t)(r0 + r) * FF + col0) = make_float4(o0, o1, o2, o3);
    }
}

// 7. CSR gather: h[i] = b + dis[i]^2*xw[i] + sum_j nrm_j * xw[src_j]  (no atomics)
__global__ void k_gather(const float* __restrict__ b) {
    int node = blockIdx.x * 8 + (threadIdx.x >> 5);
    if (node >= NN) return;
    int lane = threadIdx.x & 31;
    int f4 = lane * 4;
    float dv = g_dis[node];
    float d2 = dv * dv;
    float4 x = *(const float4*)(g_xw + (size_t)node * FF + f4);
    float4 bb = *(const float4*)(b + f4);
    float ax = bb.x + d2 * x.x;
    float ay = bb.y + d2 * x.y;
    float az = bb.z + d2 * x.z;
    float aw = bb.w + d2 * x.w;

    int j = g_off[node], j1 = g_off[node + 1];
    for (; j + 2 <= j1; j += 2) {
        int s0 = g_csr_src[j];
        int s1 = g_csr_src[j + 1];
        float n0 = g_csr_nrm[j];
        float n1 = g_csr_nrm[j + 1];
        float4 v0 = *(const float4*)(g_xw + (size_t)s0 * FF + f4);
        float4 v1 = *(const float4*)(g_xw + (size_t)s1 * FF + f4);
        ax += n0 * v0.x + n1 * v1.x;
        ay += n0 * v0.y + n1 * v1.y;
        az += n0 * v0.z + n1 * v1.z;
        aw += n0 * v0.w + n1 * v1.w;
    }
    if (j < j1) {
        int s0 = g_csr_src[j];
        float n0 = g_csr_nrm[j];
        float4 v0 = *(const float4*)(g_xw + (size_t)s0 * FF + f4);
        ax += n0 * v0.x; ay += n0 * v0.y; az += n0 * v0.z; aw += n0 * v0.w;
    }
    *(float4*)(g_h + (size_t)node * FF + f4) = make_float4(ax, ay, az, aw);
}

// 8. graph boundaries from sorted batch
__global__ void k_bounds(const int* __restrict__ batch) {
    int i = blockIdx.x * blockDim.x + threadIdx.x;
    if (i >= NN) return;
    int bv = batch[i];
    int prev = (i == 0) ? -1 : batch[i - 1];
    for (int g = prev + 1; g <= bv; ++g) g_starts[g] = i;
    if (i == NN - 1)
        for (int g = bv + 1; g <= GG; ++g) g_starts[g] = NN;
}

// 9. zero stats + flat output
__global__ void k_zero(float* __restrict__ out_flat) {
    int i = blockIdx.x * blockDim.x + threadIdx.x;
    if (i < GG * FF) { g_sum[i] = 0.0f; g_sq[i] = 0.0f; out_flat[i] = 0.0f; }
}

// 10. fused sum & sum-of-squares per (graph, feature)
__global__ void k_stats() {
    int g = blockIdx.y, c = blockIdx.x, f = threadIdx.x;
    int s = g_starts[g], e = g_starts[g + 1];
    int per = (e - s + gridDim.x - 1) / gridDim.x;
    int i0 = s + c * per;
    int i1 = min(i0 + per, e);
    float s1 = 0.0f, s2 = 0.0f;
    for (int i = i0; i < i1; ++i) {
        float v = g_h[(size_t)i * FF + f];
        s1 += v; s2 += v * v;
    }
    if (i1 > i0) {
        atomicAdd(&g_sum[g * FF + f], s1);
        atomicAdd(&g_sq[g * FF + f], s2);
    }
}

// 11. fold GraphNorm into per-(g,f) affine
__global__ void k_affine(const float* __restrict__ ms, const float* __restrict__ gnw,
                         const float* __restrict__ gnb) {
    int idx = blockIdx.x * blockDim.x + threadIdx.x;
    if (idx >= GG * FF) return;
    int g = idx >> 7, f = idx & 127;
    float cnt = fmaxf((float)(g_starts[g + 1] - g_starts[g]), 1.0f);
    float mean = g_sum[idx] / cnt;
    float m2 = mean * ms[f];
    float var = g_sq[idx] / cnt - 2.0f * m2 * mean + m2 * m2;
    var = fmaxf(var, 0.0f);
    float rstd = rsqrtf(var + EPSV);
    float sc = gnw[f] * rstd;
    g_scale[idx] = sc;
    g_shift[idx] = gnb[f] - sc * m2;
}

// 12. normalize + ReLU + h_emb + per-graph max
__global__ void k_final(float* __restrict__ out_h, float* __restrict__ out_flat) {
    int g = blockIdx.y, c = blockIdx.x, f = threadIdx.x;
    int s = g_starts[g], e = g_starts[g + 1];
    int per = (e - s + gridDim.x - 1) / gridDim.x;
    int i0 = s + c * per;
    int i1 = min(i0 + per, e);
    float sc = g_scale[g * FF + f];
    float sh = g_shift[g * FF + f];
    float m = 0.0f;
    for (int i = i0; i < i1; ++i) {
        float v = fmaxf(fmaf(g_h[(size_t)i * FF + f], sc, sh), 0.0f);
        out_h[(size_t)i * FF + f] = v;
        m = fmaxf(m, v);
    }
    if (i1 > i0) atomicMax((int*)&out_flat[g * FF + f], __float_as_int(m));
}

// 13. echo edge_index / edge_weight / batch
__global__ void k_tail(const int* __restrict__ ei, const float* __restrict__ ew,
                       const int* __restrict__ batch, float* __restrict__ out) {
    int j = blockIdx.x * blockDim.x + threadIdx.x;
    int M = 2 * NE + NE + NN;
    if (j >= M) return;
    if (j < 2 * NE)       out[OUT_EI + j] = (float)ei[j];
    else if (j < 3 * NE)  out[OUT_EW + (j - 2 * NE)] = ew[j - 2 * NE];
    else                  out[OUT_B + (j - 3 * NE)] = (float)batch[j - 3 * NE];
}

// ---------------------------------------------------------------------------
extern "C" void kernel_launch(void* const* d_in, const int* in_sizes, int n_in,
                              void* d_out, int out_size) {
    const float* X   = (const float*)d_in[0];
    const int*   ei  = (const int*)d_in[1];
    const int*   bat = (const int*)d_in[2];
    const float* ew  = (const float*)d_in[3];
    const float* W   = (const float*)d_in[4];
    const float* b   = (const float*)d_in[5];
    const float* gnw = (const float*)d_in[6];
    const float* gnb = (const float*)d_in[7];
    const float* gms = (const float*)d_in[8];
    float* out = (float*)d_out;

    const int T = 256;

    k_init<<<(NN + T - 1) / T, T>>>();
    k_deg<<<(NE + T - 1) / T, T>>>(ei, ew);
    k_rsqrt<<<(NN + T - 1) / T, T>>>();
    k_prefix<<<1, 1024>>>();
    k_csr<<<(NE + T - 1) / T, T>>>(ei, ew);

    dim3 gblk(32, 4);
    k_gemm<<<NN / 32, gblk>>>(X, W);           // 100000 % 32 == 0

    k_gather<<<(NN + 7) / 8, 256>>>(b);

    k_bounds<<<(NN + T - 1) / T, T>>>(bat);
    k_zero<<<(GG * FF + T - 1) / T, T>>>(out + OUT_FLAT);

    dim3 sgrid(16, GG);
    k_stats<<<sgrid, FF>>>();
    k_affine<<<(GG * FF + T - 1) / T, T>>>(gms, gnw, gnb);

    dim3 fgrid(32, GG);
    k_final<<<fgrid, FF>>>(out, out + OUT_FLAT);

    int tailM = 2 * NE + NE + NN;
    k_tail<<<(tailM + T - 1) / T, T>>>(ei, ew, bat, out);
}

// round 3
// speedup vs baseline: 2.2679x; 2.2679x over previous
#include <cuda_runtime.h>
#include <cuda_bf16.h>
#include <cstdint>

#define NN 100000
#define NE 1600000
#define FF 128
#define GG 64
#define EPSV 1e-5f

// Output layout (float32): h_emb [NN*FF], flat [GG*FF], edge_index [2*NE],
// edge_weight [NE], batch [NN]
#define OUT_FLAT ((size_t)NN * FF)
#define OUT_EI   (OUT_FLAT + (size_t)GG * FF)
#define OUT_EW   (OUT_EI + (size_t)2 * NE)
#define OUT_B    (OUT_EW + (size_t)NE)

// Scan geometry: 98 blocks x 256 threads x 4 items = 100352 >= NN
#define SCAN_B 98
#define SCAN_T 256
#define SCAN_I 4

// Scratch (device globals)
__device__ float g_dis[NN];
__device__ int   g_cnt[NN];
__device__ int   g_off[NN + 1];
__device__ int   g_cur[NN];
__device__ int   g_bsum[SCAN_B];
__device__ int   g_bscan[SCAN_B];
__device__ int   g_csr_src[NE];
__device__ float g_csr_nrm[NE];
__device__ float g_xw[(size_t)NN * FF];
__device__ float g_h[(size_t)NN * FF];
__device__ int   g_starts[GG + 1];
__device__ float g_sum[GG * FF];
__device__ float g_sq[GG * FF];
__device__ float g_scale[GG * FF];
__device__ float g_shift[GG * FF];

// 1. init degree (self-loop weight) + in-degree counts
__global__ void k_init() {
    int i = blockIdx.x * blockDim.x + threadIdx.x;
    if (i < NN) { g_dis[i] = 1.0f; g_cnt[i] = 0; }
}

// 2. weighted degree + integer in-degree
__global__ void k_deg(const int* __restrict__ ei, const float* __restrict__ ew) {
    int e = blockIdx.x * blockDim.x + threadIdx.x;
    if (e < NE) {
        int d = ei[NE + e];
        atomicAdd(&g_dis[d], ew[e]);
        atomicAdd(&g_cnt[d], 1);
    }
}

// 3. deg -> rsqrt(deg)
__global__ void k_rsqrt() {
    int i = blockIdx.x * blockDim.x + threadIdx.x;
    if (i < NN) g_dis[i] = rsqrtf(g_dis[i]);
}

// 4a. per-block reduce of counts
__global__ void k_scan1() {
    __shared__ int sh[SCAN_T];
    int t = threadIdx.x;
    int base = blockIdx.x * SCAN_T * SCAN_I + t * SCAN_I;
    int s = 0;
#pragma unroll
    for (int k = 0; k < SCAN_I; ++k) {
        int i = base + k;
        if (i < NN) s += g_cnt[i];
    }
    sh[t] = s;
    __syncthreads();
    for (int off = SCAN_T / 2; off > 0; off >>= 1) {
        if (t < off) sh[t] += sh[t + off];
        __syncthreads();
    }
    if (t == 0) g_bsum[blockIdx.x] = sh[0];
}

// 4b. exclusive scan of 98 block sums (one tiny block)
__global__ void k_scan2() {
    __shared__ int sh[128];
    int t = threadIdx.x;
    sh[t] = (t < SCAN_B) ? g_bsum[t] : 0;
    __syncthreads();
    for (int off = 1; off < 128; off <<= 1) {
        int v = (t >= off) ? sh[t - off] : 0;
        __syncthreads();
        sh[t] += v;
        __syncthreads();
    }
    if (t < SCAN_B) g_bscan[t] = sh[t] - g_bsum[t];   // exclusive
}

// 4c. block-local exclusive scan + base -> g_off / g_cur
__global__ void k_scan3() {
    __shared__ int sh[SCAN_T];
    int t = threadIdx.x;
    int base = blockIdx.x * SCAN_T * SCAN_I + t * SCAN_I;
    int c[SCAN_I];
    int s = 0;
#pragma unroll
    for (int k = 0; k < SCAN_I; ++k) {
        int i = base + k;
        c[k] = (i < NN) ? g_cnt[i] : 0;
        s += c[k];
    }
    sh[t] = s;
    __syncthreads();
    for (int off = 1; off < SCAN_T; off <<= 1) {
        int v = (t >= off) ? sh[t - off] : 0;
        __syncthreads();
        sh[t] += v;
        __syncthreads();
    }
    int run = g_bscan[blockIdx.x] + sh[t] - s;        // exclusive start
#pragma unroll
    for (int k = 0; k < SCAN_I; ++k) {
        int i = base + k;
        if (i < NN) { g_off[i] = run; g_cur[i] = run; }
        run += c[k];
    }
    if (blockIdx.x == 0 && t == 0) g_off[NN] = NE;
}

// 5. slot-scatter edges into CSR order, with fused norm computation
__global__ void k_csr(const int* __restrict__ ei, const float* __restrict__ ew) {
    int e = blockIdx.x * blockDim.x + threadIdx.x;
    if (e >= NE) return;
    int s = ei[e];
    int d = ei[NE + e];
    float nrm = g_dis[s] * ew[e] * g_dis[d];
    int pos = atomicAdd(&g_cur[d], 1);
    g_csr_src[pos] = s;
    g_csr_nrm[pos] = nrm;
}

// 6. xw = X @ W  — packed fp32x2 FMA, 8 rows x 4 cols per thread
__global__ __launch_bounds__(128) void k_gemm(const float* __restrict__ X,
                                              const float* __restrict__ W) {
    int lane = threadIdx.x;               // 0..31
    int ty = threadIdx.y;                 // 0..3
    int col0 = lane * 4;
    int r0 = blockIdx.x * 32 + ty * 8;
    unsigned long long acc[8][2];
#pragma unroll
    for (int r = 0; r < 8; ++r) { acc[r][0] = 0ull; acc[r][1] = 0ull; }

    for (int k4 = 0; k4 < FF; k4 += 4) {
        float4 a[8];
#pragma unroll
        for (int r = 0; r < 8; ++r)
            a[r] = *(const float4*)(X + (size_t)(r0 + r) * FF + k4);
#pragma unroll
        for (int kk = 0; kk < 4; ++kk) {
            float4 w = *(const float4*)(W + (size_t)(k4 + kk) * FF + col0);
            unsigned long long w01, w23;
            asm("mov.b64 %0,{%1,%2};" : "=l"(w01) : "f"(w.x), "f"(w.y));
            asm("mov.b64 %0,{%1,%2};" : "=l"(w23) : "f"(w.z), "f"(w.w));
#pragma unroll
            for (int r = 0; r < 8; ++r) {
                float as = ((const float*)&a[r])[kk];
                unsigned long long p;
                asm("mov.b64 %0,{%1,%1};" : "=l"(p) : "f"(as));
                asm("fma.rn.f32x2 %0,%1,%2,%0;" : "+l"(acc[r][0]) : "l"(p), "l"(w01));
                asm("fma.rn.f32x2 %0,%1,%2,%0;" : "+l"(acc[r][1]) : "l"(p), "l"(w23));
            }
        }
    }
#pragma unroll
    for (int r = 0; r < 8; ++r) {
        float o0, o1, o2, o3;
        asm("mov.b64 {%0,%1},%2;" : "=f"(o0), "=f"(o1) : "l"(acc[r][0]));
        asm("mov.b64 {%0,%1},%2;" : "=f"(o2), "=f"(o3) : "l"(acc[r][1]));
        *(float4*)(g_xw + (size_t)(r0 + r) * FF + col0) = make_float4(o0, o1, o2, o3);
    }
}

// 7. CSR gather: h[i] = b + dis[i]^2*xw[i] + sum_j nrm_j * xw[src_j]  (no atomics)
__global__ void k_gather(const float* __restrict__ b) {
    int node = blockIdx.x * 8 + (threadIdx.x >> 5);
    if (node >= NN) return;
    int lane = threadIdx.x & 31;
    int f4 = lane * 4;
    float dv = g_dis[node];
    float d2 = dv * dv;
    float4 x = *(const float4*)(g_xw + (size_t)node * FF + f4);
    float4 bb = *(const float4*)(b + f4);
    float ax = bb.x + d2 * x.x;
    float ay = bb.y + d2 * x.y;
    float az = bb.z + d2 * x.z;
    float aw = bb.w + d2 * x.w;

    int j = g_off[node], j1 = g_off[node + 1];
    for (; j + 2 <= j1; j += 2) {
        int s0 = g_csr_src[j];
        int s1 = g_csr_src[j + 1];
        float n0 = g_csr_nrm[j];
        float n1 = g_csr_nrm[j + 1];
        float4 v0 = *(const float4*)(g_xw + (size_t)s0 * FF + f4);
        float4 v1 = *(const float4*)(g_xw + (size_t)s1 * FF + f4);
        ax += n0 * v0.x + n1 * v1.x;
        ay += n0 * v0.y + n1 * v1.y;
        az += n0 * v0.z + n1 * v1.z;
        aw += n0 * v0.w + n1 * v1.w;
    }
    if (j < j1) {
        int s0 = g_csr_src[j];
        float n0 = g_csr_nrm[j];
        float4 v0 = *(const float4*)(g_xw + (size_t)s0 * FF + f4);
        ax += n0 * v0.x; ay += n0 * v0.y; az += n0 * v0.z; aw += n0 * v0.w;
    }
    *(float4*)(g_h + (size_t)node * FF + f4) = make_float4(ax, ay, az, aw);
}

// 8. graph boundaries from sorted batch
__global__ void k_bounds(const int* __restrict__ batch) {
    int i = blockIdx.x * blockDim.x + threadIdx.x;
    if (i >= NN) return;
    int bv = batch[i];
    int prev = (i == 0) ? -1 : batch[i - 1];
    for (int g = prev + 1; g <= bv; ++g) g_starts[g] = i;
    if (i == NN - 1)
        for (int g = bv + 1; g <= GG; ++g) g_starts[g] = NN;
}

// 9. zero stats + flat output
__global__ void k_zero(float* __restrict__ out_flat) {
    int i = blockIdx.x * blockDim.x + threadIdx.x;
    if (i < GG * FF) { g_sum[i] = 0.0f; g_sq[i] = 0.0f; out_flat[i] = 0.0f; }
}

// 10. fused sum & sum-of-squares per (graph, feature)
__global__ void k_stats() {
    int g = blockIdx.y, c = blockIdx.x, f = threadIdx.x;
    int s = g_starts[g], e = g_starts[g + 1];
    int per = (e - s + gridDim.x - 1) / gridDim.x;
    int i0 = s + c * per;
    int i1 = min(i0 + per, e);
    float s1 = 0.0f, s2 = 0.0f;
    for (int i = i0; i < i1; ++i) {
        float v = g_h[(size_t)i * FF + f];
        s1 += v; s2 += v * v;
    }
    if (i1 > i0) {
        atomicAdd(&g_sum[g * FF + f], s1);
        atomicAdd(&g_sq[g * FF + f], s2);
    }
}

// 11. fold GraphNorm into per-(g,f) affine
__global__ void k_affine(const float* __restrict__ ms, const float* __restrict__ gnw,
                         const float* __restrict__ gnb) {
    int idx = blockIdx.x * blockDim.x + threadIdx.x;
    if (idx >= GG * FF) return;
    int g = idx >> 7, f = idx & 127;
    float cnt = fmaxf((float)(g_starts[g + 1] - g_starts[g]), 1.0f);
    float mean = g_sum[idx] / cnt;
    float m2 = mean * ms[f];
    float var = g_sq[idx] / cnt - 2.0f * m2 * mean + m2 * m2;
    var = fmaxf(var, 0.0f);
    float rstd = rsqrtf(var + EPSV);
    float sc = gnw[f] * rstd;
    g_scale[idx] = sc;
    g_shift[idx] = gnb[f] - sc * m2;
}

// 12. normalize + ReLU + h_emb + per-graph max
__global__ void k_final(float* __restrict__ out_h, float* __restrict__ out_flat) {
    int g = blockIdx.y, c = blockIdx.x, f = threadIdx.x;
    int s = g_starts[g], e = g_starts[g + 1];
    int per = (e - s + gridDim.x - 1) / gridDim.x;
    int i0 = s + c * per;
    int i1 = min(i0 + per, e);
    float sc = g_scale[g * FF + f];
    float sh = g_shift[g * FF + f];
    float m = 0.0f;
    for (int i = i0; i < i1; ++i) {
        float v = fmaxf(fmaf(g_h[(size_t)i * FF + f], sc, sh), 0.0f);
        out_h[(size_t)i * FF + f] = v;
        m = fmaxf(m, v);
    }
    if (i1 > i0) atomicMax((int*)&out_flat[g * FF + f], __float_as_int(m));
}

// 13. echo edge_index / edge_weight / batch
__global__ void k_tail(const int* __restrict__ ei, const float* __restrict__ ew,
                       const int* __restrict__ batch, float* __restrict__ out) {
    int j = blockIdx.x * blockDim.x + threadIdx.x;
    int M = 2 * NE + NE + NN;
    if (j >= M) return;
    if (j < 2 * NE)       out[OUT_EI + j] = (float)ei[j];
    else if (j < 3 * NE)  out[OUT_EW + (j - 2 * NE)] = ew[j - 2 * NE];
    else                  out[OUT_B + (j - 3 * NE)] = (float)batch[j - 3 * NE];
}

// ---------------------------------------------------------------------------
extern "C" void kernel_launch(void* const* d_in, const int* in_sizes, int n_in,
                              void* d_out, int out_size) {
    const float* X   = (const float*)d_in[0];
    const int*   ei  = (const int*)d_in[1];
    const int*   bat = (const int*)d_in[2];
    const float* ew  = (const float*)d_in[3];
    const float* W   = (const float*)d_in[4];
    const float* b   = (const float*)d_in[5];
    const float* gnw = (const float*)d_in[6];
    const float* gnb = (const float*)d_in[7];
    const float* gms = (const float*)d_in[8];
    float* out = (float*)d_out;

    const int T = 256;

    k_init<<<(NN + T - 1) / T, T>>>();
    k_deg<<<(NE + T - 1) / T, T>>>(ei, ew);
    k_rsqrt<<<(NN + T - 1) / T, T>>>();

    k_scan1<<<SCAN_B, SCAN_T>>>();
    k_scan2<<<1, 128>>>();
    k_scan3<<<SCAN_B, SCAN_T>>>();

    k_csr<<<(NE + T - 1) / T, T>>>(ei, ew);

    dim3 gblk(32, 4);
    k_gemm<<<NN / 32, gblk>>>(X, W);           // 100000 % 32 == 0

    k_gather<<<(NN + 7) / 8, 256>>>(b);

    k_bounds<<<(NN + T - 1) / T, T>>>(bat);
    k_zero<<<(GG * FF + T - 1) / T, T>>>(out + OUT_FLAT);

    dim3 sgrid(16, GG);
    k_stats<<<sgrid, FF>>>();
    k_affine<<<(GG * FF + T - 1) / T, T>>>(gms, gnw, gnb);

    dim3 fgrid(32, GG);
    k_final<<<fgrid, FF>>>(out, out + OUT_FLAT);

    int tailM = 2 * NE + NE + NN;
    k_tail<<<(tailM + T - 1) / T, T>>>(ei, ew, bat, out);
}

// round 4
// speedup vs baseline: 2.5922x; 1.1430x over previous
#include <cuda_runtime.h>
#include <cuda_fp16.h>
#include <cstdint>

#define NN 100000
#define NE 1600000
#define FF 128
#define GG 64
#define EPSV 1e-5f

// Output layout (float32): h_emb [NN*FF], flat [GG*FF], edge_index [2*NE],
// edge_weight [NE], batch [NN]
#define OUT_FLAT ((size_t)NN * FF)
#define OUT_EI   (OUT_FLAT + (size_t)GG * FF)
#define OUT_EW   (OUT_EI + (size_t)2 * NE)
#define OUT_B    (OUT_EW + (size_t)NE)

// Scan geometry: 98 blocks x 256 threads x 4 items = 100352 >= NN
#define SCAN_B 98
#define SCAN_T 256
#define SCAN_I 4

// Scratch (device globals)
__device__ float  g_dis[NN];
__device__ int    g_cnt[NN];
__device__ int    g_off[NN + 1];
__device__ int    g_cur[NN];
__device__ int    g_bsum[SCAN_B];
__device__ int    g_bscan[SCAN_B];
__device__ int2   g_csr[NE];                    // {src, float_as_int(norm)}
__device__ __half g_xw[(size_t)NN * FF];        // X @ W  (fp16)
__device__ float  g_h[(size_t)NN * FF];
__device__ int    g_starts[GG + 1];
__device__ float  g_sum[GG * FF];
__device__ float  g_sq[GG * FF];
__device__ float  g_scale[GG * FF];
__device__ float  g_shift[GG * FF];

// 1. init degree (self-loop weight) + in-degree counts
__global__ void k_init() {
    int i = blockIdx.x * blockDim.x + threadIdx.x;
    if (i < NN) { g_dis[i] = 1.0f; g_cnt[i] = 0; }
}

// 2. weighted degree + integer in-degree
__global__ void k_deg(const int* __restrict__ ei, const float* __restrict__ ew) {
    int e = blockIdx.x * blockDim.x + threadIdx.x;
    if (e < NE) {
        int d = ei[NE + e];
        atomicAdd(&g_dis[d], ew[e]);
        atomicAdd(&g_cnt[d], 1);
    }
}

// 3. deg -> rsqrt(deg)
__global__ void k_rsqrt() {
    int i = blockIdx.x * blockDim.x + threadIdx.x;
    if (i < NN) g_dis[i] = rsqrtf(g_dis[i]);
}

// 4a. per-block reduce of counts
__global__ void k_scan1() {
    __shared__ int sh[SCAN_T];
    int t = threadIdx.x;
    int base = blockIdx.x * SCAN_T * SCAN_I + t * SCAN_I;
    int s = 0;
#pragma unroll
    for (int k = 0; k < SCAN_I; ++k) {
        int i = base + k;
        if (i < NN) s += g_cnt[i];
    }
    sh[t] = s;
    __syncthreads();
    for (int off = SCAN_T / 2; off > 0; off >>= 1) {
        if (t < off) sh[t] += sh[t + off];
        __syncthreads();
    }
    if (t == 0) g_bsum[blockIdx.x] = sh[0];
}

// 4b. exclusive scan of 98 block sums
__global__ void k_scan2() {
    __shared__ int sh[128];
    int t = threadIdx.x;
    sh[t] = (t < SCAN_B) ? g_bsum[t] : 0;
    __syncthreads();
    for (int off = 1; off < 128; off <<= 1) {
        int v = (t >= off) ? sh[t - off] : 0;
        __syncthreads();
        sh[t] += v;
        __syncthreads();
    }
    if (t < SCAN_B) g_bscan[t] = sh[t] - g_bsum[t];
}

// 4c. block-local exclusive scan + base -> g_off / g_cur
__global__ void k_scan3() {
    __shared__ int sh[SCAN_T];
    int t = threadIdx.x;
    int base = blockIdx.x * SCAN_T * SCAN_I + t * SCAN_I;
    int c[SCAN_I];
    int s = 0;
#pragma unroll
    for (int k = 0; k < SCAN_I; ++k) {
        int i = base + k;
        c[k] = (i < NN) ? g_cnt[i] : 0;
        s += c[k];
    }
    sh[t] = s;
    __syncthreads();
    for (int off = 1; off < SCAN_T; off <<= 1) {
        int v = (t >= off) ? sh[t - off] : 0;
        __syncthreads();
        sh[t] += v;
        __syncthreads();
    }
    int run = g_bscan[blockIdx.x] + sh[t] - s;
#pragma unroll
    for (int k = 0; k < SCAN_I; ++k) {
        int i = base + k;
        if (i < NN) { g_off[i] = run; g_cur[i] = run; }
        run += c[k];
    }
    if (blockIdx.x == 0 && t == 0) g_off[NN] = NE;
}

// 5. slot-scatter edges into CSR order with fused norm
__global__ void k_csr(const int* __restrict__ ei, const float* __restrict__ ew) {
    int e = blockIdx.x * blockDim.x + threadIdx.x;
    if (e >= NE) return;
    int s = ei[e];
    int d = ei[NE + e];
    float nrm = g_dis[s] * ew[e] * g_dis[d];
    int pos = atomicAdd(&g_cur[d], 1);
    g_csr[pos] = make_int2(s, __float_as_int(nrm));
}

// 6. xw = X @ W  — packed fp32x2 FMA, fp16 output
__global__ __launch_bounds__(128) void k_gemm(const float* __restrict__ X,
                                              const float* __restrict__ W) {
    int lane = threadIdx.x;
    int ty = threadIdx.y;
    int col0 = lane * 4;
    int r0 = blockIdx.x * 32 + ty * 8;
    unsigned long long acc[8][2];
#pragma unroll
    for (int r = 0; r < 8; ++r) { acc[r][0] = 0ull; acc[r][1] = 0ull; }

    for (int k4 = 0; k4 < FF; k4 += 4) {
        float4 a[8];
#pragma unroll
        for (int r = 0; r < 8; ++r)
            a[r] = *(const float4*)(X + (size_t)(r0 + r) * FF + k4);
#pragma unroll
        for (int kk = 0; kk < 4; ++kk) {
            float4 w = *(const float4*)(W + (size_t)(k4 + kk) * FF + col0);
            unsigned long long w01, w23;
            asm("mov.b64 %0,{%1,%2};" : "=l"(w01) : "f"(w.x), "f"(w.y));
            asm("mov.b64 %0,{%1,%2};" : "=l"(w23) : "f"(w.z), "f"(w.w));
#pragma unroll
            for (int r = 0; r < 8; ++r) {
                float as = ((const float*)&a[r])[kk];
                unsigned long long p;
                asm("mov.b64 %0,{%1,%1};" : "=l"(p) : "f"(as));
                asm("fma.rn.f32x2 %0,%1,%2,%0;" : "+l"(acc[r][0]) : "l"(p), "l"(w01));
                asm("fma.rn.f32x2 %0,%1,%2,%0;" : "+l"(acc[r][1]) : "l"(p), "l"(w23));
            }
        }
    }
#pragma unroll
    for (int r = 0; r < 8; ++r) {
        float o0, o1, o2, o3;
        asm("mov.b64 {%0,%1},%2;" : "=f"(o0), "=f"(o1) : "l"(acc[r][0]));
        asm("mov.b64 {%0,%1},%2;" : "=f"(o2), "=f"(o3) : "l"(acc[r][1]));
        __half2 h0 = __floats2half2_rn(o0, o1);
        __half2 h1 = __floats2half2_rn(o2, o3);
        uint2 pk;
        pk.x = *(unsigned int*)&h0;
        pk.y = *(unsigned int*)&h1;
        *((uint2*)(g_xw + (size_t)(r0 + r) * FF) + lane) = pk;
    }
}

// helper: fp16 row fragment (4 feats) -> 4 floats
__device__ __forceinline__ float4 ld_row_h(int node, int lane) {
    uint2 r = *((const uint2*)(g_xw + (size_t)node * FF) + lane);
    __half2 h0 = *reinterpret_cast<__half2*>(&r.x);
    __half2 h1 = *reinterpret_cast<__half2*>(&r.y);
    float2 f0 = __half22float2(h0);
    float2 f1 = __half22float2(h1);
    return make_float4(f0.x, f0.y, f1.x, f1.y);
}

// 7. CSR gather (no atomics), 4-edge unroll for MLP
__global__ void k_gather(const float* __restrict__ b) {
    int node = blockIdx.x * 8 + (threadIdx.x >> 5);
    if (node >= NN) return;
    int lane = threadIdx.x & 31;
    float dv = g_dis[node];
    float d2 = dv * dv;
    float4 x = ld_row_h(node, lane);
    float4 bb = *(const float4*)(b + lane * 4);
    float ax = bb.x + d2 * x.x;
    float ay = bb.y + d2 * x.y;
    float az = bb.z + d2 * x.z;
    float aw = bb.w + d2 * x.w;

    int j = g_off[node], j1 = g_off[node + 1];
    for (; j + 4 <= j1; j += 4) {
        int2 e0 = g_csr[j], e1 = g_csr[j + 1], e2 = g_csr[j + 2], e3 = g_csr[j + 3];
        float4 v0 = ld_row_h(e0.x, lane);
        float4 v1 = ld_row_h(e1.x, lane);
        float4 v2 = ld_row_h(e2.x, lane);
        float4 v3 = ld_row_h(e3.x, lane);
        float n0 = __int_as_float(e0.y), n1 = __int_as_float(e1.y);
        float n2 = __int_as_float(e2.y), n3 = __int_as_float(e3.y);
        ax += n0 * v0.x + n1 * v1.x + n2 * v2.x + n3 * v3.x;
        ay += n0 * v0.y + n1 * v1.y + n2 * v2.y + n3 * v3.y;
        az += n0 * v0.z + n1 * v1.z + n2 * v2.z + n3 * v3.z;
        aw += n0 * v0.w + n1 * v1.w + n2 * v2.w + n3 * v3.w;
    }
    for (; j < j1; ++j) {
        int2 e0 = g_csr[j];
        float n0 = __int_as_float(e0.y);
        float4 v0 = ld_row_h(e0.x, lane);
        ax += n0 * v0.x; ay += n0 * v0.y; az += n0 * v0.z; aw += n0 * v0.w;
    }
    *(float4*)(g_h + (size_t)node * FF + lane * 4) = make_float4(ax, ay, az, aw);
}

// 8. graph boundaries from sorted batch
__global__ void k_bounds(const int* __restrict__ batch) {
    int i = blockIdx.x * blockDim.x + threadIdx.x;
    if (i >= NN) return;
    int bv = batch[i];
    int prev = (i == 0) ? -1 : batch[i - 1];
    for (int g = prev + 1; g <= bv; ++g) g_starts[g] = i;
    if (i == NN - 1)
        for (int g = bv + 1; g <= GG; ++g) g_starts[g] = NN;
}

// 9. zero stats + flat output
__global__ void k_zero(float* __restrict__ out_flat) {
    int i = blockIdx.x * blockDim.x + threadIdx.x;
    if (i < GG * FF) { g_sum[i] = 0.0f; g_sq[i] = 0.0f; out_flat[i] = 0.0f; }
}

// 10. fused sum & sum-of-squares per (graph, feature)
__global__ void k_stats() {
    int g = blockIdx.y, c = blockIdx.x, f = threadIdx.x;
    int s = g_starts[g], e = g_starts[g + 1];
    int per = (e - s + gridDim.x - 1) / gridDim.x;
    int i0 = s + c * per;
    int i1 = min(i0 + per, e);
    float s1 = 0.0f, s2 = 0.0f;
    for (int i = i0; i < i1; ++i) {
        float v = g_h[(size_t)i * FF + f];
        s1 += v; s2 += v * v;
    }
    if (i1 > i0) {
        atomicAdd(&g_sum[g * FF + f], s1);
        atomicAdd(&g_sq[g * FF + f], s2);
    }
}

// 11. fold GraphNorm into per-(g,f) affine
__global__ void k_affine(const float* __restrict__ ms, const float* __restrict__ gnw,
                         const float* __restrict__ gnb) {
    int idx = blockIdx.x * blockDim.x + threadIdx.x;
    if (idx >= GG * FF) return;
    int g = idx >> 7, f = idx & 127;
    float cnt = fmaxf((float)(g_starts[g + 1] - g_starts[g]), 1.0f);
    float mean = g_sum[idx] / cnt;
    float m2 = mean * ms[f];
    float var = g_sq[idx] / cnt - 2.0f * m2 * mean + m2 * m2;
    var = fmaxf(var, 0.0f);
    float rstd = rsqrtf(var + EPSV);
    float sc = gnw[f] * rstd;
    g_scale[idx] = sc;
    g_shift[idx] = gnb[f] - sc * m2;
}

// 12. normalize + ReLU + h_emb + per-graph max
__global__ void k_final(float* __restrict__ out_h, float* __restrict__ out_flat) {
    int g = blockIdx.y, c = blockIdx.x, f = threadIdx.x;
    int s = g_starts[g], e = g_starts[g + 1];
    int per = (e - s + gridDim.x - 1) / gridDim.x;
    int i0 = s + c * per;
    int i1 = min(i0 + per, e);
    float sc = g_scale[g * FF + f];
    float sh = g_shift[g * FF + f];
    float m = 0.0f;
    for (int i = i0; i < i1; ++i) {
        float v = fmaxf(fmaf(g_h[(size_t)i * FF + f], sc, sh), 0.0f);
        out_h[(size_t)i * FF + f] = v;
        m = fmaxf(m, v);
    }
    if (i1 > i0) atomicMax((int*)&out_flat[g * FF + f], __float_as_int(m));
}

// 13. echo edge_index / edge_weight / batch
__global__ void k_tail(const int* __restrict__ ei, const float* __restrict__ ew,
                       const int* __restrict__ batch, float* __restrict__ out) {
    int j = blockIdx.x * blockDim.x + threadIdx.x;
    int M = 2 * NE + NE + NN;
    if (j >= M) return;
    if (j < 2 * NE)       out[OUT_EI + j] = (float)ei[j];
    else if (j < 3 * NE)  out[OUT_EW + (j - 2 * NE)] = ew[j - 2 * NE];
    else                  out[OUT_B + (j - 3 * NE)] = (float)batch[j - 3 * NE];
}

// ---------------------------------------------------------------------------
extern "C" void kernel_launch(void* const* d_in, const int* in_sizes, int n_in,
                              void* d_out, int out_size) {
    const float* X   = (const float*)d_in[0];
    const int*   ei  = (const int*)d_in[1];
    const int*   bat = (const int*)d_in[2];
    const float* ew  = (const float*)d_in[3];
    const float* W   = (const float*)d_in[4];
    const float* b   = (const float*)d_in[5];
    const float* gnw = (const float*)d_in[6];
    const float* gnb = (const float*)d_in[7];
    const float* gms = (const float*)d_in[8];
    float* out = (float*)d_out;

    const int T = 256;

    k_init<<<(NN + T - 1) / T, T>>>();
    k_deg<<<(NE + T - 1) / T, T>>>(ei, ew);
    k_rsqrt<<<(NN + T - 1) / T, T>>>();

    k_scan1<<<SCAN_B, SCAN_T>>>();
    k_scan2<<<1, 128>>>();
    k_scan3<<<SCAN_B, SCAN_T>>>();

    k_csr<<<(NE + T - 1) / T, T>>>(ei, ew);

    dim3 gblk(32, 4);
    k_gemm<<<NN / 32, gblk>>>(X, W);

    k_gather<<<(NN + 7) / 8, 256>>>(b);

    k_bounds<<<(NN + T - 1) / T, T>>>(bat);
    k_zero<<<(GG * FF + T - 1) / T, T>>>(out + OUT_FLAT);

    dim3 sgrid(16, GG);
    k_stats<<<sgrid, FF>>>();
    k_affine<<<(GG * FF + T - 1) / T, T>>>(gms, gnw, gnb);

    dim3 fgrid(32, GG);
    k_final<<<fgrid, FF>>>(out, out + OUT_FLAT);

    int tailM = 2 * NE + NE + NN;
    k_tail<<<(tailM + T - 1) / T, T>>>(ei, ew, bat, out);
}

// round 5
// speedup vs baseline: 3.6331x; 1.4016x over previous
#include <cuda_runtime.h>
#include <cuda_fp16.h>
#include <cstdint>

#define NN 100000
#define NE 1600000
#define FF 128
#define GG 64
#define EPSV 1e-5f

// Output layout (float32): h_emb [NN*FF], flat [GG*FF], edge_index [2*NE],
// edge_weight [NE], batch [NN]
#define OUT_FLAT ((size_t)NN * FF)
#define OUT_EI   (OUT_FLAT + (size_t)GG * FF)
#define OUT_EW   (OUT_EI + (size_t)2 * NE)
#define OUT_B    (OUT_EW + (size_t)NE)

#define SCAN_B 98
#define SCAN_T 256
#define SCAN_I 4

// Scratch (device globals)
__device__ float  g_dis[NN];
__device__ int    g_cnt[NN];
__device__ int    g_off[NN + 1];
__device__ int    g_cur[NN];
__device__ int    g_bsum[SCAN_B];
__device__ int    g_bscan[SCAN_B];
__device__ int2   g_csr[NE];                    // {src, float_as_int(norm)}
__device__ __half g_xw[(size_t)NN * FF];        // X @ W  (fp16)
__device__ float  g_h[(size_t)NN * FF];
__device__ int    g_starts[GG + 1];
__device__ float  g_sum[GG * FF];
__device__ float  g_sq[GG * FF];
__device__ float  g_scale[GG * FF];
__device__ float  g_shift[GG * FF];

// 1. init
__global__ void k_init() {
    int i = blockIdx.x * blockDim.x + threadIdx.x;
    if (i < NN) { g_dis[i] = 1.0f; g_cnt[i] = 0; }
}

// 2. weighted degree + integer in-degree
__global__ void k_deg(const int* __restrict__ ei, const float* __restrict__ ew) {
    int e = blockIdx.x * blockDim.x + threadIdx.x;
    if (e < NE) {
        int d = ei[NE + e];
        atomicAdd(&g_dis[d], ew[e]);
        atomicAdd(&g_cnt[d], 1);
    }
}

// 3. deg -> rsqrt(deg)
__global__ void k_rsqrt() {
    int i = blockIdx.x * blockDim.x + threadIdx.x;
    if (i < NN) g_dis[i] = rsqrtf(g_dis[i]);
}

// 4a. per-block reduce of counts
__global__ void k_scan1() {
    __shared__ int sh[SCAN_T];
    int t = threadIdx.x;
    int base = blockIdx.x * SCAN_T * SCAN_I + t * SCAN_I;
    int s = 0;
#pragma unroll
    for (int k = 0; k < SCAN_I; ++k) {
        int i = base + k;
        if (i < NN) s += g_cnt[i];
    }
    sh[t] = s;
    __syncthreads();
    for (int off = SCAN_T / 2; off > 0; off >>= 1) {
        if (t < off) sh[t] += sh[t + off];
        __syncthreads();
    }
    if (t == 0) g_bsum[blockIdx.x] = sh[0];
}

// 4b. exclusive scan of 98 block sums
__global__ void k_scan2() {
    __shared__ int sh[128];
    int t = threadIdx.x;
    sh[t] = (t < SCAN_B) ? g_bsum[t] : 0;
    __syncthreads();
    for (int off = 1; off < 128; off <<= 1) {
        int v = (t >= off) ? sh[t - off] : 0;
        __syncthreads();
        sh[t] += v;
        __syncthreads();
    }
    if (t < SCAN_B) g_bscan[t] = sh[t] - g_bsum[t];
}

// 4c. block-local exclusive scan + base
__global__ void k_scan3() {
    __shared__ int sh[SCAN_T];
    int t = threadIdx.x;
    int base = blockIdx.x * SCAN_T * SCAN_I + t * SCAN_I;
    int c[SCAN_I];
    int s = 0;
#pragma unroll
    for (int k = 0; k < SCAN_I; ++k) {
        int i = base + k;
        c[k] = (i < NN) ? g_cnt[i] : 0;
        s += c[k];
    }
    sh[t] = s;
    __syncthreads();
    for (int off = 1; off < SCAN_T; off <<= 1) {
        int v = (t >= off) ? sh[t - off] : 0;
        __syncthreads();
        sh[t] += v;
        __syncthreads();
    }
    int run = g_bscan[blockIdx.x] + sh[t] - s;
#pragma unroll
    for (int k = 0; k < SCAN_I; ++k) {
        int i = base + k;
        if (i < NN) { g_off[i] = run; g_cur[i] = run; }
        run += c[k];
    }
    if (blockIdx.x == 0 && t == 0) g_off[NN] = NE;
}

// 5. slot-scatter edges into CSR order with fused norm
__global__ void k_csr(const int* __restrict__ ei, const float* __restrict__ ew) {
    int e = blockIdx.x * blockDim.x + threadIdx.x;
    if (e >= NE) return;
    int s = ei[e];
    int d = ei[NE + e];
    float nrm = g_dis[s] * ew[e] * g_dis[d];
    int pos = atomicAdd(&g_cur[d], 1);
    g_csr[pos] = make_int2(s, __float_as_int(nrm));
}

// helpers ---------------------------------------------------------------
__device__ __forceinline__ unsigned f2h2(float a, float b) {
    __half2 h = __floats2half2_rn(a, b);
    return *(unsigned*)&h;
}

// 6. xw = X @ W  — HMMA m16n8k16, fp16 in / fp32 accum / fp16 out
// block: 256 threads (8 warps), tile 128 rows; warp w owns rows [w*16,w*16+16)
__global__ __launch_bounds__(256) void k_gemm(const float* __restrict__ X,
                                              const float* __restrict__ W) {
    __shared__ __half2 Wp[64][136];   // Wp[kp][n] = (W[2kp][n], W[2kp+1][n]); pad 8
    int tid = threadIdx.x;
    int r0 = blockIdx.x * 128;

    // load W k-pair-interleaved (each block; W is L2-resident)
    for (int idx = tid; idx < 64 * 32; idx += 256) {
        int kp = idx >> 5;
        int n4 = (idx & 31) * 4;
        float4 w0 = *(const float4*)(W + (size_t)(2 * kp) * FF + n4);
        float4 w1 = *(const float4*)(W + (size_t)(2 * kp + 1) * FF + n4);
        Wp[kp][n4 + 0] = __floats2half2_rn(w0.x, w1.x);
        Wp[kp][n4 + 1] = __floats2half2_rn(w0.y, w1.y);
        Wp[kp][n4 + 2] = __floats2half2_rn(w0.z, w1.z);
        Wp[kp][n4 + 3] = __floats2half2_rn(w0.w, w1.w);
    }
    __syncthreads();

    int warp = tid >> 5, lane = tid & 31;
    int gid = lane >> 2;            // 0..7
    int tig = lane & 3;             // 0..3
    int r_lo = r0 + warp * 16 + gid;
    int r_hi = r_lo + 8;
    bool vlo = r_lo < NN, vhi = r_hi < NN;
    const float2* plo = (const float2*)(X + (size_t)r_lo * FF);
    const float2* phi = (const float2*)(X + (size_t)r_hi * FF);
    int c2 = tig;                   // float2 index of col 2*tig

    float acc[16][4];
#pragma unroll
    for (int nt = 0; nt < 16; ++nt)
#pragma unroll
        for (int q = 0; q < 4; ++q) acc[nt][q] = 0.0f;

#pragma unroll
    for (int kk = 0; kk < 8; ++kk) {
        int k0 = kk * 16;
        int kb = k0 >> 1;           // float2 / half2-pair base
        float2 z = make_float2(0.f, 0.f);
        float2 f0 = vlo ? plo[kb + c2]     : z;
        float2 f1 = vhi ? phi[kb + c2]     : z;
        float2 f2 = vlo ? plo[kb + c2 + 4] : z;
        float2 f3 = vhi ? phi[kb + c2 + 4] : z;
        unsigned a0 = f2h2(f0.x, f0.y);
        unsigned a1 = f2h2(f1.x, f1.y);
        unsigned a2 = f2h2(f2.x, f2.y);
        unsigned a3 = f2h2(f3.x, f3.y);
        int kp = kb + tig;
#pragma unroll
        for (int nt = 0; nt < 16; ++nt) {
            int n = nt * 8 + gid;
            unsigned b0 = *(unsigned*)&Wp[kp][n];
            unsigned b1 = *(unsigned*)&Wp[kp + 4][n];
            asm volatile(
                "mma.sync.aligned.m16n8k16.row.col.f32.f16.f16.f32 "
                "{%0,%1,%2,%3},{%4,%5,%6,%7},{%8,%9},{%0,%1,%2,%3};"
                : "+f"(acc[nt][0]), "+f"(acc[nt][1]), "+f"(acc[nt][2]), "+f"(acc[nt][3])
                : "r"(a0), "r"(a1), "r"(a2), "r"(a3), "r"(b0), "r"(b1));
        }
    }

    // store D as fp16
#pragma unroll
    for (int nt = 0; nt < 16; ++nt) {
        int col = nt * 8 + tig * 2;
        if (vlo) {
            __half2 h = __floats2half2_rn(acc[nt][0], acc[nt][1]);
            *(__half2*)(g_xw + (size_t)r_lo * FF + col) = h;
        }
        if (vhi) {
            __half2 h = __floats2half2_rn(acc[nt][2], acc[nt][3]);
            *(__half2*)(g_xw + (size_t)r_hi * FF + col) = h;
        }
    }
}

// fp16 row fragment (4 feats) -> 4 floats
__device__ __forceinline__ float4 ld_row_h(int node, int lane) {
    uint2 r = *((const uint2*)(g_xw + (size_t)node * FF) + lane);
    __half2 h0 = *reinterpret_cast<__half2*>(&r.x);
    __half2 h1 = *reinterpret_cast<__half2*>(&r.y);
    float2 f0 = __half22float2(h0);
    float2 f1 = __half22float2(h1);
    return make_float4(f0.x, f0.y, f1.x, f1.y);
}

// 7. CSR gather (no atomics), 4-edge unroll
__global__ void k_gather(const float* __restrict__ b) {
    int node = blockIdx.x * 8 + (threadIdx.x >> 5);
    if (node >= NN) return;
    int lane = threadIdx.x & 31;
    float dv = g_dis[node];
    float d2 = dv * dv;
    float4 x = ld_row_h(node, lane);
    float4 bb = *(const float4*)(b + lane * 4);
    float ax = bb.x + d2 * x.x;
    float ay = bb.y + d2 * x.y;
    float az = bb.z + d2 * x.z;
    float aw = bb.w + d2 * x.w;

    int j = g_off[node], j1 = g_off[node + 1];
    for (; j + 4 <= j1; j += 4) {
        int2 e0 = g_csr[j], e1 = g_csr[j + 1], e2 = g_csr[j + 2], e3 = g_csr[j + 3];
        float4 v0 = ld_row_h(e0.x, lane);
        float4 v1 = ld_row_h(e1.x, lane);
        float4 v2 = ld_row_h(e2.x, lane);
        float4 v3 = ld_row_h(e3.x, lane);
        float n0 = __int_as_float(e0.y), n1 = __int_as_float(e1.y);
        float n2 = __int_as_float(e2.y), n3 = __int_as_float(e3.y);
        ax += n0 * v0.x + n1 * v1.x + n2 * v2.x + n3 * v3.x;
        ay += n0 * v0.y + n1 * v1.y + n2 * v2.y + n3 * v3.y;
        az += n0 * v0.z + n1 * v1.z + n2 * v2.z + n3 * v3.z;
        aw += n0 * v0.w + n1 * v1.w + n2 * v2.w + n3 * v3.w;
    }
    for (; j < j1; ++j) {
        int2 e0 = g_csr[j];
        float n0 = __int_as_float(e0.y);
        float4 v0 = ld_row_h(e0.x, lane);
        ax += n0 * v0.x; ay += n0 * v0.y; az += n0 * v0.z; aw += n0 * v0.w;
    }
    *(float4*)(g_h + (size_t)node * FF + lane * 4) = make_float4(ax, ay, az, aw);
}

// 8. graph boundaries from sorted batch
__global__ void k_bounds(const int* __restrict__ batch) {
    int i = blockIdx.x * blockDim.x + threadIdx.x;
    if (i >= NN) return;
    int bv = batch[i];
    int prev = (i == 0) ? -1 : batch[i - 1];
    for (int g = prev + 1; g <= bv; ++g) g_starts[g] = i;
    if (i == NN - 1)
        for (int g = bv + 1; g <= GG; ++g) g_starts[g] = NN;
}

// 9. zero stats + flat output
__global__ void k_zero(float* __restrict__ out_flat) {
    int i = blockIdx.x * blockDim.x + threadIdx.x;
    if (i < GG * FF) { g_sum[i] = 0.0f; g_sq[i] = 0.0f; out_flat[i] = 0.0f; }
}

// 10. fused sum & sum-of-squares
__global__ void k_stats() {
    int g = blockIdx.y, c = blockIdx.x, f = threadIdx.x;
    int s = g_starts[g], e = g_starts[g + 1];
    int per = (e - s + gridDim.x - 1) / gridDim.x;
    int i0 = s + c * per;
    int i1 = min(i0 + per, e);
    float s1 = 0.0f, s2 = 0.0f;
    for (int i = i0; i < i1; ++i) {
        float v = g_h[(size_t)i * FF + f];
        s1 += v; s2 += v * v;
    }
    if (i1 > i0) {
        atomicAdd(&g_sum[g * FF + f], s1);
        atomicAdd(&g_sq[g * FF + f], s2);
    }
}

// 11. fold GraphNorm into per-(g,f) affine
__global__ void k_affine(const float* __restrict__ ms, const float* __restrict__ gnw,
                         const float* __restrict__ gnb) {
    int idx = blockIdx.x * blockDim.x + threadIdx.x;
    if (idx >= GG * FF) return;
    int g = idx >> 7, f = idx & 127;
    float cnt = fmaxf((float)(g_starts[g + 1] - g_starts[g]), 1.0f);
    float mean = g_sum[idx] / cnt;
    float m2 = mean * ms[f];
    float var = g_sq[idx] / cnt - 2.0f * m2 * mean + m2 * m2;
    var = fmaxf(var, 0.0f);
    float rstd = rsqrtf(var + EPSV);
    float sc = gnw[f] * rstd;
    g_scale[idx] = sc;
    g_shift[idx] = gnb[f] - sc * m2;
}

// 12. normalize + ReLU + h_emb + per-graph max
__global__ void k_final(float* __restrict__ out_h, float* __restrict__ out_flat) {
    int g = blockIdx.y, c = blockIdx.x, f = threadIdx.x;
    int s = g_starts[g], e = g_starts[g + 1];
    int per = (e - s + gridDim.x - 1) / gridDim.x;
    int i0 = s + c * per;
    int i1 = min(i0 + per, e);
    float sc = g_scale[g * FF + f];
    float sh = g_shift[g * FF + f];
    float m = 0.0f;
    for (int i = i0; i < i1; ++i) {
        float v = fmaxf(fmaf(g_h[(size_t)i * FF + f], sc, sh), 0.0f);
        out_h[(size_t)i * FF + f] = v;
        m = fmaxf(m, v);
    }
    if (i1 > i0) atomicMax((int*)&out_flat[g * FF + f], __float_as_int(m));
}

// 13. echo edge_index / edge_weight / batch
__global__ void k_tail(const int* __restrict__ ei, const float* __restrict__ ew,
                       const int* __restrict__ batch, float* __restrict__ out) {
    int j = blockIdx.x * blockDim.x + threadIdx.x;
    int M = 2 * NE + NE + NN;
    if (j >= M) return;
    if (j < 2 * NE)       out[OUT_EI + j] = (float)ei[j];
    else if (j < 3 * NE)  out[OUT_EW + (j - 2 * NE)] = ew[j - 2 * NE];
    else                  out[OUT_B + (j - 3 * NE)] = (float)batch[j - 3 * NE];
}

// ---------------------------------------------------------------------------
extern "C" void kernel_launch(void* const* d_in, const int* in_sizes, int n_in,
                              void* d_out, int out_size) {
    const float* X   = (const float*)d_in[0];
    const int*   ei  = (const int*)d_in[1];
    const int*   bat = (const int*)d_in[2];
    const float* ew  = (const float*)d_in[3];
    const float* W   = (const float*)d_in[4];
    const float* b   = (const float*)d_in[5];
    const float* gnw = (const float*)d_in[6];
    const float* gnb = (const float*)d_in[7];
    const float* gms = (const float*)d_in[8];
    float* out = (float*)d_out;

    const int T = 256;

    k_init<<<(NN + T - 1) / T, T>>>();
    k_deg<<<(NE + T - 1) / T, T>>>(ei, ew);
    k_rsqrt<<<(NN + T - 1) / T, T>>>();

    k_scan1<<<SCAN_B, SCAN_T>>>();
    k_scan2<<<1, 128>>>();
    k_scan3<<<SCAN_B, SCAN_T>>>();

    k_csr<<<(NE + T - 1) / T, T>>>(ei, ew);

    k_gemm<<<(NN + 127) / 128, 256>>>(X, W);

    k_gather<<<(NN + 7) / 8, 256>>>(b);

    k_bounds<<<(NN + T - 1) / T, T>>>(bat);
    k_zero<<<(GG * FF + T - 1) / T, T>>>(out + OUT_FLAT);

    dim3 sgrid(16, GG);
    k_stats<<<sgrid, FF>>>();
    k_affine<<<(GG * FF + T - 1) / T, T>>>(gms, gnw, gnb);

    dim3 fgrid(32, GG);
    k_final<<<fgrid, FF>>>(out, out + OUT_FLAT);

    int tailM = 2 * NE + NE + NN;
    k_tail<<<(tailM + T - 1) / T, T>>>(ei, ew, bat, out);
}

// round 6
// speedup vs baseline: 3.6422x; 1.0025x over previous
#include <cuda_runtime.h>
#include <cuda_fp16.h>
#include <cstdint>

#define NN 100000
#define NE 1600000
#define FF 128
#define GG 64
#define EPSV 1e-5f

// Output layout (float32): h_emb [NN*FF], flat [GG*FF], edge_index [2*NE],
// edge_weight [NE], batch [NN]
#define OUT_FLAT ((size_t)NN * FF)
#define OUT_EI   (OUT_FLAT + (size_t)GG * FF)
#define OUT_EW   (OUT_EI + (size_t)2 * NE)
#define OUT_B    (OUT_EW + (size_t)NE)

#define SCAN_B 98
#define SCAN_T 256
#define SCAN_I 4

#define FIXS 268435456.0f    /* 2^28 */
#define FIXR 3.7252902984619140625e-9f  /* 2^-28 */

// Scratch (device globals)
__device__ unsigned long long g_pack[NN];   // count<<40 | q28 weighted degree
__device__ float  g_dis[NN];
__device__ int    g_cnt[NN];
__device__ int    g_off[NN + 1];
__device__ int    g_cur[NN];
__device__ int    g_bsum[SCAN_B];
__device__ int    g_bscan[SCAN_B];
__device__ int2   g_csr[NE];                    // {src, float_as_int(norm)}
__device__ __half g_xw[(size_t)NN * FF];        // X @ W  (fp16)
__device__ float  g_h[(size_t)NN * FF];
__device__ int    g_starts[GG + 1];
__device__ float  g_sum[GG * FF];
__device__ float  g_sq[GG * FF];
__device__ float  g_scale[GG * FF];
__device__ float  g_shift[GG * FF];

// 1. init: self-loop weight 1.0 in fixed point, count 0
__global__ void k_init() {
    int i = blockIdx.x * blockDim.x + threadIdx.x;
    if (i < NN) g_pack[i] = (unsigned long long)(1u << 28);
}

// 2. one packed 64-bit atomic per edge: ++count, sum += q28(ew)
__global__ void k_deg(const int* __restrict__ ei, const float* __restrict__ ew) {
    int e = blockIdx.x * blockDim.x + threadIdx.x;
    if (e < NE) {
        int d = ei[NE + e];
        unsigned long long q = (unsigned long long)__float2uint_rn(ew[e] * FIXS);
        atomicAdd(&g_pack[d], (1ull << 40) | q);
    }
}

// 3. unpack -> rsqrt(deg), cnt
__global__ void k_rsqrt() {
    int i = blockIdx.x * blockDim.x + threadIdx.x;
    if (i < NN) {
        unsigned long long p = g_pack[i];
        g_cnt[i] = (int)(p >> 40);
        float deg = (float)(p & 0xFFFFFFFFFFull) * FIXR;
        g_dis[i] = rsqrtf(deg);
    }
}

// 4a. per-block reduce of counts
__global__ void k_scan1() {
    __shared__ int sh[SCAN_T];
    int t = threadIdx.x;
    int base = blockIdx.x * SCAN_T * SCAN_I + t * SCAN_I;
    int s = 0;
#pragma unroll
    for (int k = 0; k < SCAN_I; ++k) {
        int i = base + k;
        if (i < NN) s += g_cnt[i];
    }
    sh[t] = s;
    __syncthreads();
    for (int off = SCAN_T / 2; off > 0; off >>= 1) {
        if (t < off) sh[t] += sh[t + off];
        __syncthreads();
    }
    if (t == 0) g_bsum[blockIdx.x] = sh[0];
}

// 4b. exclusive scan of 98 block sums
__global__ void k_scan2() {
    __shared__ int sh[128];
    int t = threadIdx.x;
    sh[t] = (t < SCAN_B) ? g_bsum[t] : 0;
    __syncthreads();
    for (int off = 1; off < 128; off <<= 1) {
        int v = (t >= off) ? sh[t - off] : 0;
        __syncthreads();
        sh[t] += v;
        __syncthreads();
    }
    if (t < SCAN_B) g_bscan[t] = sh[t] - g_bsum[t];
}

// 4c. block-local exclusive scan + base
__global__ void k_scan3() {
    __shared__ int sh[SCAN_T];
    int t = threadIdx.x;
    int base = blockIdx.x * SCAN_T * SCAN_I + t * SCAN_I;
    int c[SCAN_I];
    int s = 0;
#pragma unroll
    for (int k = 0; k < SCAN_I; ++k) {
        int i = base + k;
        c[k] = (i < NN) ? g_cnt[i] : 0;
        s += c[k];
    }
    sh[t] = s;
    __syncthreads();
    for (int off = 1; off < SCAN_T; off <<= 1) {
        int v = (t >= off) ? sh[t - off] : 0;
        __syncthreads();
        sh[t] += v;
        __syncthreads();
    }
    int run = g_bscan[blockIdx.x] + sh[t] - s;
#pragma unroll
    for (int k = 0; k < SCAN_I; ++k) {
        int i = base + k;
        if (i < NN) { g_off[i] = run; g_cur[i] = run; }
        run += c[k];
    }
    if (blockIdx.x == 0 && t == 0) g_off[NN] = NE;
}

// 5. slot-scatter edges into CSR order with fused norm
__global__ void k_csr(const int* __restrict__ ei, const float* __restrict__ ew) {
    int e = blockIdx.x * blockDim.x + threadIdx.x;
    if (e >= NE) return;
    int s = ei[e];
    int d = ei[NE + e];
    float nrm = g_dis[s] * ew[e] * g_dis[d];
    int pos = atomicAdd(&g_cur[d], 1);
    g_csr[pos] = make_int2(s, __float_as_int(nrm));
}

// helpers ---------------------------------------------------------------
__device__ __forceinline__ unsigned f2h2(float a, float b) {
    __half2 h = __floats2half2_rn(a, b);
    return *(unsigned*)&h;
}

// 6. xw = X @ W  — HMMA m16n8k16, fp16 in / fp32 accum / fp16 out
__global__ __launch_bounds__(256) void k_gemm(const float* __restrict__ X,
                                              const float* __restrict__ W) {
    __shared__ __half2 Wp[64][136];   // Wp[kp][n] = (W[2kp][n], W[2kp+1][n])
    int tid = threadIdx.x;
    int r0 = blockIdx.x * 128;

    for (int idx = tid; idx < 64 * 32; idx += 256) {
        int kp = idx >> 5;
        int n4 = (idx & 31) * 4;
        float4 w0 = *(const float4*)(W + (size_t)(2 * kp) * FF + n4);
        float4 w1 = *(const float4*)(W + (size_t)(2 * kp + 1) * FF + n4);
        Wp[kp][n4 + 0] = __floats2half2_rn(w0.x, w1.x);
        Wp[kp][n4 + 1] = __floats2half2_rn(w0.y, w1.y);
        Wp[kp][n4 + 2] = __floats2half2_rn(w0.z, w1.z);
        Wp[kp][n4 + 3] = __floats2half2_rn(w0.w, w1.w);
    }
    __syncthreads();

    int warp = tid >> 5, lane = tid & 31;
    int gid = lane >> 2;
    int tig = lane & 3;
    int r_lo = r0 + warp * 16 + gid;
    int r_hi = r_lo + 8;
    bool vlo = r_lo < NN, vhi = r_hi < NN;
    const float2* plo = (const float2*)(X + (size_t)r_lo * FF);
    const float2* phi = (const float2*)(X + (size_t)r_hi * FF);
    int c2 = tig;

    float acc[16][4];
#pragma unroll
    for (int nt = 0; nt < 16; ++nt)
#pragma unroll
        for (int q = 0; q < 4; ++q) acc[nt][q] = 0.0f;

#pragma unroll
    for (int kk = 0; kk < 8; ++kk) {
        int kb = kk * 8;
        float2 z = make_float2(0.f, 0.f);
        float2 f0 = vlo ? plo[kb + c2]     : z;
        float2 f1 = vhi ? phi[kb + c2]     : z;
        float2 f2 = vlo ? plo[kb + c2 + 4] : z;
        float2 f3 = vhi ? phi[kb + c2 + 4] : z;
        unsigned a0 = f2h2(f0.x, f0.y);
        unsigned a1 = f2h2(f1.x, f1.y);
        unsigned a2 = f2h2(f2.x, f2.y);
        unsigned a3 = f2h2(f3.x, f3.y);
        int kp = kb + tig;
#pragma unroll
        for (int nt = 0; nt < 16; ++nt) {
            int n = nt * 8 + gid;
            unsigned b0 = *(unsigned*)&Wp[kp][n];
            unsigned b1 = *(unsigned*)&Wp[kp + 4][n];
            asm volatile(
                "mma.sync.aligned.m16n8k16.row.col.f32.f16.f16.f32 "
                "{%0,%1,%2,%3},{%4,%5,%6,%7},{%8,%9},{%0,%1,%2,%3};"
                : "+f"(acc[nt][0]), "+f"(acc[nt][1]), "+f"(acc[nt][2]), "+f"(acc[nt][3])
                : "r"(a0), "r"(a1), "r"(a2), "r"(a3), "r"(b0), "r"(b1));
        }
    }

#pragma unroll
    for (int nt = 0; nt < 16; ++nt) {
        int col = nt * 8 + tig * 2;
        if (vlo) {
            __half2 h = __floats2half2_rn(acc[nt][0], acc[nt][1]);
            *(__half2*)(g_xw + (size_t)r_lo * FF + col) = h;
        }
        if (vhi) {
            __half2 h = __floats2half2_rn(acc[nt][2], acc[nt][3]);
            *(__half2*)(g_xw + (size_t)r_hi * FF + col) = h;
        }
    }
}

// fp16 row fragment (4 feats) -> 4 floats
__device__ __forceinline__ float4 ld_row_h(int node, int lane) {
    uint2 r = *((const uint2*)(g_xw + (size_t)node * FF) + lane);
    __half2 h0 = *reinterpret_cast<__half2*>(&r.x);
    __half2 h1 = *reinterpret_cast<__half2*>(&r.y);
    float2 f0 = __half22float2(h0);
    float2 f1 = __half22float2(h1);
    return make_float4(f0.x, f0.y, f1.x, f1.y);
}

// 7. CSR gather (no atomics), 8-edge unroll for MLP
__global__ __launch_bounds__(256) void k_gather(const float* __restrict__ b) {
    int node = blockIdx.x * 8 + (threadIdx.x >> 5);
    if (node >= NN) return;
    int lane = threadIdx.x & 31;
    float dv = g_dis[node];
    float d2 = dv * dv;
    float4 x = ld_row_h(node, lane);
    float4 bb = *(const float4*)(b + lane * 4);
    float ax = bb.x + d2 * x.x;
    float ay = bb.y + d2 * x.y;
    float az = bb.z + d2 * x.z;
    float aw = bb.w + d2 * x.w;

    int j = g_off[node], j1 = g_off[node + 1];
    for (; j + 8 <= j1; j += 8) {
        int2 e[8];
        float4 v[8];
#pragma unroll
        for (int q = 0; q < 8; ++q) e[q] = g_csr[j + q];
#pragma unroll
        for (int q = 0; q < 8; ++q) v[q] = ld_row_h(e[q].x, lane);
#pragma unroll
        for (int q = 0; q < 8; ++q) {
            float n = __int_as_float(e[q].y);
            ax += n * v[q].x;
            ay += n * v[q].y;
            az += n * v[q].z;
            aw += n * v[q].w;
        }
    }
    for (; j + 2 <= j1; j += 2) {
        int2 e0 = g_csr[j], e1 = g_csr[j + 1];
        float4 v0 = ld_row_h(e0.x, lane);
        float4 v1 = ld_row_h(e1.x, lane);
        float n0 = __int_as_float(e0.y), n1 = __int_as_float(e1.y);
        ax += n0 * v0.x + n1 * v1.x;
        ay += n0 * v0.y + n1 * v1.y;
        az += n0 * v0.z + n1 * v1.z;
        aw += n0 * v0.w + n1 * v1.w;
    }
    if (j < j1) {
        int2 e0 = g_csr[j];
        float n0 = __int_as_float(e0.y);
        float4 v0 = ld_row_h(e0.x, lane);
        ax += n0 * v0.x; ay += n0 * v0.y; az += n0 * v0.z; aw += n0 * v0.w;
    }
    *(float4*)(g_h + (size_t)node * FF + lane * 4) = make_float4(ax, ay, az, aw);
}

// 8. graph boundaries from sorted batch
__global__ void k_bounds(const int* __restrict__ batch) {
    int i = blockIdx.x * blockDim.x + threadIdx.x;
    if (i >= NN) return;
    int bv = batch[i];
    int prev = (i == 0) ? -1 : batch[i - 1];
    for (int g = prev + 1; g <= bv; ++g) g_starts[g] = i;
    if (i == NN - 1)
        for (int g = bv + 1; g <= GG; ++g) g_starts[g] = NN;
}

// 9. zero stats + flat output
__global__ void k_zero(float* __restrict__ out_flat) {
    int i = blockIdx.x * blockDim.x + threadIdx.x;
    if (i < GG * FF) { g_sum[i] = 0.0f; g_sq[i] = 0.0f; out_flat[i] = 0.0f; }
}

// 10. fused sum & sum-of-squares
__global__ void k_stats() {
    int g = blockIdx.y, c = blockIdx.x, f = threadIdx.x;
    int s = g_starts[g], e = g_starts[g + 1];
    int per = (e - s + gridDim.x - 1) / gridDim.x;
    int i0 = s + c * per;
    int i1 = min(i0 + per, e);
    float s1 = 0.0f, s2 = 0.0f;
    for (int i = i0; i < i1; ++i) {
        float v = g_h[(size_t)i * FF + f];
        s1 += v; s2 += v * v;
    }
    if (i1 > i0) {
        atomicAdd(&g_sum[g * FF + f], s1);
        atomicAdd(&g_sq[g * FF + f], s2);
    }
}

// 11. fold GraphNorm into per-(g,f) affine
__global__ void k_affine(const float* __restrict__ ms, const float* __restrict__ gnw,
                         const float* __restrict__ gnb) {
    int idx = blockIdx.x * blockDim.x + threadIdx.x;
    if (idx >= GG * FF) return;
    int g = idx >> 7, f = idx & 127;
    float cnt = fmaxf((float)(g_starts[g + 1] - g_starts[g]), 1.0f);
    float mean = g_sum[idx] / cnt;
    float m2 = mean * ms[f];
    float var = g_sq[idx] / cnt - 2.0f * m2 * mean + m2 * m2;
    var = fmaxf(var, 0.0f);
    float rstd = rsqrtf(var + EPSV);
    float sc = gnw[f] * rstd;
    g_scale[idx] = sc;
    g_shift[idx] = gnb[f] - sc * m2;
}

// 12. normalize + ReLU + h_emb + per-graph max
__global__ void k_final(float* __restrict__ out_h, float* __restrict__ out_flat) {
    int g = blockIdx.y, c = blockIdx.x, f = threadIdx.x;
    int s = g_starts[g], e = g_starts[g + 1];
    int per = (e - s + gridDim.x - 1) / gridDim.x;
    int i0 = s + c * per;
    int i1 = min(i0 + per, e);
    float sc = g_scale[g * FF + f];
    float sh = g_shift[g * FF + f];
    float m = 0.0f;
    for (int i = i0; i < i1; ++i) {
        float v = fmaxf(fmaf(g_h[(size_t)i * FF + f], sc, sh), 0.0f);
        out_h[(size_t)i * FF + f] = v;
        m = fmaxf(m, v);
    }
    if (i1 > i0) atomicMax((int*)&out_flat[g * FF + f], __float_as_int(m));
}

// 13. echo edge_index / edge_weight / batch
__global__ void k_tail(const int* __restrict__ ei, const float* __restrict__ ew,
                       const int* __restrict__ batch, float* __restrict__ out) {
    int j = blockIdx.x * blockDim.x + threadIdx.x;
    int M = 2 * NE + NE + NN;
    if (j >= M) return;
    if (j < 2 * NE)       out[OUT_EI + j] = (float)ei[j];
    else if (j < 3 * NE)  out[OUT_EW + (j - 2 * NE)] = ew[j - 2 * NE];
    else                  out[OUT_B + (j - 3 * NE)] = (float)batch[j - 3 * NE];
}

// ---------------------------------------------------------------------------
extern "C" void kernel_launch(void* const* d_in, const int* in_sizes, int n_in,
                              void* d_out, int out_size) {
    const float* X   = (const float*)d_in[0];
    const int*   ei  = (const int*)d_in[1];
    const int*   bat = (const int*)d_in[2];
    const float* ew  = (const float*)d_in[3];
    const float* W   = (const float*)d_in[4];
    const float* b   = (const float*)d_in[5];
    const float* gnw = (const float*)d_in[6];
    const float* gnb = (const float*)d_in[7];
    const float* gms = (const float*)d_in[8];
    float* out = (float*)d_out;

    const int T = 256;

    k_init<<<(NN + T - 1) / T, T>>>();
    k_deg<<<(NE + T - 1) / T, T>>>(ei, ew);
    k_rsqrt<<<(NN + T - 1) / T, T>>>();

    k_scan1<<<SCAN_B, SCAN_T>>>();
    k_scan2<<<1, 128>>>();
    k_scan3<<<SCAN_B, SCAN_T>>>();

    k_csr<<<(NE + T - 1) / T, T>>>(ei, ew);

    k_gemm<<<(NN + 127) / 128, 256>>>(X, W);

    k_gather<<<(NN + 7) / 8, 256>>>(b);

    k_bounds<<<(NN + T - 1) / T, T>>>(bat);
    k_zero<<<(GG * FF + T - 1) / T, T>>>(out + OUT_FLAT);

    dim3 sgrid(16, GG);
    k_stats<<<sgrid, FF>>>();
    k_affine<<<(GG * FF + T - 1) / T, T>>>(gms, gnw, gnb);

    dim3 fgrid(32, GG);
    k_final<<<fgrid, FF>>>(out, out + OUT_FLAT);

    int tailM = 2 * NE + NE + NN;
    k_tail<<<(tailM + T - 1) / T, T>>>(ei, ew, bat, out);
}

// round 7
// speedup vs baseline: 3.9086x; 1.0731x over previous
#include <cuda_runtime.h>
#include <cuda_fp16.h>
#include <cstdint>

#define NN 100000
#define NE 1600000
#define FF 128
#define GG 64
#define EPSV 1e-5f

// Output layout (float32): h_emb [NN*FF], flat [GG*FF], edge_index [2*NE],
// edge_weight [NE], batch [NN]
#define OUT_FLAT ((size_t)NN * FF)
#define OUT_EI   (OUT_FLAT + (size_t)GG * FF)
#define OUT_EW   (OUT_EI + (size_t)2 * NE)
#define OUT_B    (OUT_EW + (size_t)NE)

#define SCAN_B 98
#define SCAN_T 256
#define SCAN_I 4

#define FIXS 268435456.0f               /* 2^28 */
#define FIXR 3.7252902984619140625e-9f /* 2^-28 */

// Scratch (device globals)
__device__ unsigned long long g_pack[NN];   // count<<40 | q28 weighted degree
__device__ unsigned short g_slot[NE];       // slot of edge within dst bucket
__device__ float  g_dis[NN];
__device__ int    g_cnt[NN];
__device__ int    g_off[NN + 1];
__device__ int    g_bsum[SCAN_B];
__device__ int    g_bscan[SCAN_B];
__device__ int2   g_csr[NE];                // {src, float_as_int(norm)}
__device__ __half g_xw[(size_t)NN * FF];    // X @ W  (fp16)
__device__ __half g_hh[(size_t)NN * FF];    // aggregated h (fp16)
__device__ int    g_starts[GG + 1];
__device__ float  g_sum[GG * FF];
__device__ float  g_sq[GG * FF];
__device__ float  g_scale[GG * FF];
__device__ float  g_shift[GG * FF];

// 1. init: self-loop weight 1.0 in fixed point, count 0
__global__ void k_init() {
    int i = blockIdx.x * blockDim.x + threadIdx.x;
    if (i < NN) g_pack[i] = (unsigned long long)(1u << 28);
}

// 2. one packed 64-bit atomic per edge; capture slot from returned old value
__global__ void k_deg(const int* __restrict__ ei, const float* __restrict__ ew) {
    int e = blockIdx.x * blockDim.x + threadIdx.x;
    if (e < NE) {
        int d = ei[NE + e];
        unsigned long long q = (unsigned long long)__float2uint_rn(ew[e] * FIXS);
        unsigned long long old = atomicAdd(&g_pack[d], (1ull << 40) | q);
        g_slot[e] = (unsigned short)(old >> 40);
    }
}

// 3a. per-block reduce of counts; also unpack -> dis/cnt (absorbs old k_rsqrt)
__global__ void k_scan1() {
    __shared__ int sh[SCAN_T];
    int t = threadIdx.x;
    int base = blockIdx.x * SCAN_T * SCAN_I + t * SCAN_I;
    int s = 0;
#pragma unroll
    for (int k = 0; k < SCAN_I; ++k) {
        int i = base + k;
        if (i < NN) {
            unsigned long long p = g_pack[i];
            int c = (int)(p >> 40);
            g_cnt[i] = c;
            g_dis[i] = rsqrtf((float)(p & 0xFFFFFFFFFFull) * FIXR);
            s += c;
        }
    }
    sh[t] = s;
    __syncthreads();
    for (int off = SCAN_T / 2; off > 0; off >>= 1) {
        if (t < off) sh[t] += sh[t + off];
        __syncthreads();
    }
    if (t == 0) g_bsum[blockIdx.x] = sh[0];
}

// 3b. exclusive scan of 98 block sums
__global__ void k_scan2() {
    __shared__ int sh[128];
    int t = threadIdx.x;
    sh[t] = (t < SCAN_B) ? g_bsum[t] : 0;
    __syncthreads();
    for (int off = 1; off < 128; off <<= 1) {
        int v = (t >= off) ? sh[t - off] : 0;
        __syncthreads();
        sh[t] += v;
        __syncthreads();
    }
    if (t < SCAN_B) g_bscan[t] = sh[t] - g_bsum[t];
}

// 3c. block-local exclusive scan + base -> g_off
__global__ void k_scan3() {
    __shared__ int sh[SCAN_T];
    int t = threadIdx.x;
    int base = blockIdx.x * SCAN_T * SCAN_I + t * SCAN_I;
    int c[SCAN_I];
    int s = 0;
#pragma unroll
    for (int k = 0; k < SCAN_I; ++k) {
        int i = base + k;
        c[k] = (i < NN) ? g_cnt[i] : 0;
        s += c[k];
    }
    sh[t] = s;
    __syncthreads();
    for (int off = 1; off < SCAN_T; off <<= 1) {
        int v = (t >= off) ? sh[t - off] : 0;
        __syncthreads();
        sh[t] += v;
        __syncthreads();
    }
    int run = g_bscan[blockIdx.x] + sh[t] - s;
#pragma unroll
    for (int k = 0; k < SCAN_I; ++k) {
        int i = base + k;
        if (i < NN) g_off[i] = run;
        run += c[k];
    }
    if (blockIdx.x == 0 && t == 0) g_off[NN] = NE;
}

// 4. CSR fill — atomic-free (slot precomputed), fused norm
__global__ void k_csr(const int* __restrict__ ei, const float* __restrict__ ew) {
    int e = blockIdx.x * blockDim.x + threadIdx.x;
    if (e >= NE) return;
    int s = ei[e];
    int d = ei[NE + e];
    float nrm = g_dis[s] * ew[e] * g_dis[d];
    int pos = g_off[d] + (int)g_slot[e];
    g_csr[pos] = make_int2(s, __float_as_int(nrm));
}

// helpers ---------------------------------------------------------------
__device__ __forceinline__ unsigned f2h2(float a, float b) {
    __half2 h = __floats2half2_rn(a, b);
    return *(unsigned*)&h;
}

// 5. xw = X @ W  — HMMA m16n8k16, fp16 in / fp32 accum / fp16 out
__global__ __launch_bounds__(256) void k_gemm(const float* __restrict__ X,
                                              const float* __restrict__ W) {
    __shared__ __half2 Wp[64][136];   // Wp[kp][n] = (W[2kp][n], W[2kp+1][n])
    int tid = threadIdx.x;
    int r0 = blockIdx.x * 128;

    for (int idx = tid; idx < 64 * 32; idx += 256) {
        int kp = idx >> 5;
        int n4 = (idx & 31) * 4;
        float4 w0 = *(const float4*)(W + (size_t)(2 * kp) * FF + n4);
        float4 w1 = *(const float4*)(W + (size_t)(2 * kp + 1) * FF + n4);
        Wp[kp][n4 + 0] = __floats2half2_rn(w0.x, w1.x);
        Wp[kp][n4 + 1] = __floats2half2_rn(w0.y, w1.y);
        Wp[kp][n4 + 2] = __floats2half2_rn(w0.z, w1.z);
        Wp[kp][n4 + 3] = __floats2half2_rn(w0.w, w1.w);
    }
    __syncthreads();

    int warp = tid >> 5, lane = tid & 31;
    int gid = lane >> 2;
    int tig = lane & 3;
    int r_lo = r0 + warp * 16 + gid;
    int r_hi = r_lo + 8;
    bool vlo = r_lo < NN, vhi = r_hi < NN;
    const float2* plo = (const float2*)(X + (size_t)r_lo * FF);
    const float2* phi = (const float2*)(X + (size_t)r_hi * FF);
    int c2 = tig;

    float acc[16][4];
#pragma unroll
    for (int nt = 0; nt < 16; ++nt)
#pragma unroll
        for (int q = 0; q < 4; ++q) acc[nt][q] = 0.0f;

#pragma unroll
    for (int kk = 0; kk < 8; ++kk) {
        int kb = kk * 8;
        float2 z = make_float2(0.f, 0.f);
        float2 f0 = vlo ? plo[kb + c2]     : z;
        float2 f1 = vhi ? phi[kb + c2]     : z;
        float2 f2 = vlo ? plo[kb + c2 + 4] : z;
        float2 f3 = vhi ? phi[kb + c2 + 4] : z;
        unsigned a0 = f2h2(f0.x, f0.y);
        unsigned a1 = f2h2(f1.x, f1.y);
        unsigned a2 = f2h2(f2.x, f2.y);
        unsigned a3 = f2h2(f3.x, f3.y);
        int kp = kb + tig;
#pragma unroll
        for (int nt = 0; nt < 16; ++nt) {
            int n = nt * 8 + gid;
            unsigned b0 = *(unsigned*)&Wp[kp][n];
            unsigned b1 = *(unsigned*)&Wp[kp + 4][n];
            asm volatile(
                "mma.sync.aligned.m16n8k16.row.col.f32.f16.f16.f32 "
                "{%0,%1,%2,%3},{%4,%5,%6,%7},{%8,%9},{%0,%1,%2,%3};"
                : "+f"(acc[nt][0]), "+f"(acc[nt][1]), "+f"(acc[nt][2]), "+f"(acc[nt][3])
                : "r"(a0), "r"(a1), "r"(a2), "r"(a3), "r"(b0), "r"(b1));
        }
    }

#pragma unroll
    for (int nt = 0; nt < 16; ++nt) {
        int col = nt * 8 + tig * 2;
        if (vlo) {
            __half2 h = __floats2half2_rn(acc[nt][0], acc[nt][1]);
            *(__half2*)(g_xw + (size_t)r_lo * FF + col) = h;
        }
        if (vhi) {
            __half2 h = __floats2half2_rn(acc[nt][2], acc[nt][3]);
            *(__half2*)(g_xw + (size_t)r_hi * FF + col) = h;
        }
    }
}

// fp16 row fragment (4 feats) -> 4 floats
__device__ __forceinline__ float4 ld_row_h(int node, int lane) {
    uint2 r = *((const uint2*)(g_xw + (size_t)node * FF) + lane);
    __half2 h0 = *reinterpret_cast<__half2*>(&r.x);
    __half2 h1 = *reinterpret_cast<__half2*>(&r.y);
    float2 f0 = __half22float2(h0);
    float2 f1 = __half22float2(h1);
    return make_float4(f0.x, f0.y, f1.x, f1.y);
}

// 6. CSR gather (no atomics), fp16 h output
__global__ __launch_bounds__(256) void k_gather(const float* __restrict__ b) {
    int node = blockIdx.x * 8 + (threadIdx.x >> 5);
    if (node >= NN) return;
    int lane = threadIdx.x & 31;
    float dv = g_dis[node];
    float d2 = dv * dv;
    float4 x = ld_row_h(node, lane);
    float4 bb = *(const float4*)(b + lane * 4);
    float ax = bb.x + d2 * x.x;
    float ay = bb.y + d2 * x.y;
    float az = bb.z + d2 * x.z;
    float aw = bb.w + d2 * x.w;

    int j = g_off[node], j1 = g_off[node + 1];
    for (; j + 4 <= j1; j += 4) {
        int2 e0 = g_csr[j], e1 = g_csr[j + 1], e2 = g_csr[j + 2], e3 = g_csr[j + 3];
        float4 v0 = ld_row_h(e0.x, lane);
        float4 v1 = ld_row_h(e1.x, lane);
        float4 v2 = ld_row_h(e2.x, lane);
        float4 v3 = ld_row_h(e3.x, lane);
        float n0 = __int_as_float(e0.y), n1 = __int_as_float(e1.y);
        float n2 = __int_as_float(e2.y), n3 = __int_as_float(e3.y);
        ax += n0 * v0.x + n1 * v1.x + n2 * v2.x + n3 * v3.x;
        ay += n0 * v0.y + n1 * v1.y + n2 * v2.y + n3 * v3.y;
        az += n0 * v0.z + n1 * v1.z + n2 * v2.z + n3 * v3.z;
        aw += n0 * v0.w + n1 * v1.w + n2 * v2.w + n3 * v3.w;
    }
    for (; j < j1; ++j) {
        int2 e0 = g_csr[j];
        float n0 = __int_as_float(e0.y);
        float4 v0 = ld_row_h(e0.x, lane);
        ax += n0 * v0.x; ay += n0 * v0.y; az += n0 * v0.z; aw += n0 * v0.w;
    }
    uint2 pk;
    pk.x = f2h2(ax, ay);
    pk.y = f2h2(az, aw);
    *((uint2*)(g_hh + (size_t)node * FF) + lane) = pk;
}

// 7. graph boundaries from sorted batch
__global__ void k_bounds(const int* __restrict__ batch) {
    int i = blockIdx.x * blockDim.x + threadIdx.x;
    if (i >= NN) return;
    int bv = batch[i];
    int prev = (i == 0) ? -1 : batch[i - 1];
    for (int g = prev + 1; g <= bv; ++g) g_starts[g] = i;
    if (i == NN - 1)
        for (int g = bv + 1; g <= GG; ++g) g_starts[g] = NN;
}

// 8. zero stats + flat output
__global__ void k_zero(float* __restrict__ out_flat) {
    int i = blockIdx.x * blockDim.x + threadIdx.x;
    if (i < GG * FF) { g_sum[i] = 0.0f; g_sq[i] = 0.0f; out_flat[i] = 0.0f; }
}

// 9. fused sum & sum-of-squares (reads fp16 h)
__global__ void k_stats() {
    int g = blockIdx.y, c = blockIdx.x, f = threadIdx.x;
    int s = g_starts[g], e = g_starts[g + 1];
    int per = (e - s + gridDim.x - 1) / gridDim.x;
    int i0 = s + c * per;
    int i1 = min(i0 + per, e);
    float s1 = 0.0f, s2 = 0.0f;
    for (int i = i0; i < i1; ++i) {
        float v = __half2float(g_hh[(size_t)i * FF + f]);
        s1 += v; s2 += v * v;
    }
    if (i1 > i0) {
        atomicAdd(&g_sum[g * FF + f], s1);
        atomicAdd(&g_sq[g * FF + f], s2);
    }
}

// 10. fold GraphNorm into per-(g,f) affine
__global__ void k_affine(const float* __restrict__ ms, const float* __restrict__ gnw,
                         const float* __restrict__ gnb) {
    int idx = blockIdx.x * blockDim.x + threadIdx.x;
    if (idx >= GG * FF) return;
    int g = idx >> 7, f = idx & 127;
    float cnt = fmaxf((float)(g_starts[g + 1] - g_starts[g]), 1.0f);
    float mean = g_sum[idx] / cnt;
    float m2 = mean * ms[f];
    float var = g_sq[idx] / cnt - 2.0f * m2 * mean + m2 * m2;
    var = fmaxf(var, 0.0f);
    float rstd = rsqrtf(var + EPSV);
    float sc = gnw[f] * rstd;
    g_scale[idx] = sc;
    g_shift[idx] = gnb[f] - sc * m2;
}

// 11. normalize + ReLU + h_emb + per-graph max (reads fp16 h)
__global__ void k_final(float* __restrict__ out_h, float* __restrict__ out_flat) {
    int g = blockIdx.y, c = blockIdx.x, f = threadIdx.x;
    int s = g_starts[g], e = g_starts[g + 1];
    int per = (e - s + gridDim.x - 1) / gridDim.x;
    int i0 = s + c * per;
    int i1 = min(i0 + per, e);
    float sc = g_scale[g * FF + f];
    float sh = g_shift[g * FF + f];
    float m = 0.0f;
    for (int i = i0; i < i1; ++i) {
        float hv = __half2float(g_hh[(size_t)i * FF + f]);
        float v = fmaxf(fmaf(hv, sc, sh), 0.0f);
        out_h[(size_t)i * FF + f] = v;
        m = fmaxf(m, v);
    }
    if (i1 > i0) atomicMax((int*)&out_flat[g * FF + f], __float_as_int(m));
}

// 12. echo edge_index / edge_weight / batch
__global__ void k_tail(const int* __restrict__ ei, const float* __restrict__ ew,
                       const int* __restrict__ batch, float* __restrict__ out) {
    int j = blockIdx.x * blockDim.x + threadIdx.x;
    int M = 2 * NE + NE + NN;
    if (j >= M) return;
    if (j < 2 * NE)       out[OUT_EI + j] = (float)ei[j];
    else if (j < 3 * NE)  out[OUT_EW + (j - 2 * NE)] = ew[j - 2 * NE];
    else                  out[OUT_B + (j - 3 * NE)] = (float)batch[j - 3 * NE];
}

// ---------------------------------------------------------------------------
extern "C" void kernel_launch(void* const* d_in, const int* in_sizes, int n_in,
                              void* d_out, int out_size) {
    const float* X   = (const float*)d_in[0];
    const int*   ei  = (const int*)d_in[1];
    const int*   bat = (const int*)d_in[2];
    const float* ew  = (const float*)d_in[3];
    const float* W   = (const float*)d_in[4];
    const float* b   = (const float*)d_in[5];
    const float* gnw = (const float*)d_in[6];
    const float* gnb = (const float*)d_in[7];
    const float* gms = (const float*)d_in[8];
    float* out = (float*)d_out;

    const int T = 256;

    k_init<<<(NN + T - 1) / T, T>>>();
    k_deg<<<(NE + T - 1) / T, T>>>(ei, ew);

    k_scan1<<<SCAN_B, SCAN_T>>>();
    k_scan2<<<1, 128>>>();
    k_scan3<<<SCAN_B, SCAN_T>>>();

    k_csr<<<(NE + T - 1) / T, T>>>(ei, ew);

    k_gemm<<<(NN + 127) / 128, 256>>>(X, W);

    k_gather<<<(NN + 7) / 8, 256>>>(b);

    k_bounds<<<(NN + T - 1) / T, T>>>(bat);
    k_zero<<<(GG * FF + T - 1) / T, T>>>(out + OUT_FLAT);

    dim3 sgrid(16, GG);
    k_stats<<<sgrid, FF>>>();
    k_affine<<<(GG * FF + T - 1) / T, T>>>(gms, gnw, gnb);

    dim3 fgrid(32, GG);
    k_final<<<fgrid, FF>>>(out, out + OUT_FLAT);

    int tailM = 2 * NE + NE + NN;
    k_tail<<<(tailM + T - 1) / T, T>>>(ei, ew, bat, out);
}

// round 8
// speedup vs baseline: 4.1513x; 1.0621x over previous
#include <cuda_runtime.h>
#include <cuda_fp16.h>
#include <cstdint>

#define NN 100000
#define NE 1600000
#define FF 128
#define GG 64
#define EPSV 1e-5f

// Output layout (float32): h_emb [NN*FF], flat [GG*FF], edge_index [2*NE],
// edge_weight [NE], batch [NN]
#define OUT_FLAT ((size_t)NN * FF)
#define OUT_EI   (OUT_FLAT + (size_t)GG * FF)
#define OUT_EW   (OUT_EI + (size_t)2 * NE)
#define OUT_B    (OUT_EW + (size_t)NE)

#define SCAN_B 98
#define SCAN_T 256
#define SCAN_I 4

#define FIXS 268435456.0f               /* 2^28 */
#define FIXR 3.7252902984619140625e-9f /* 2^-28 */

// block-dispatch geometry
#define INIT_B   391                     /* ceil(NN/256) */
#define ZERO_B   32                      /* GG*FF/256 */
#define BOUNDS_B 391
#define DEG_B    6250                    /* NE/256 */
#define TAILV    1225000                 /* (2NE + NE + NN)/4 */
#define TAIL_B   4786                    /* ceil(TAILV/256) */
#define GEMM_B   782                     /* ceil(NN/128) */
#define CSR_B    6250

// Scratch (device globals)
__device__ unsigned long long g_pack[NN];   // count<<40 | q28 weighted degree
__device__ unsigned short g_slot[NE];       // slot of edge within dst bucket
__device__ float  g_dis[NN];
__device__ int    g_cnt[NN];
__device__ int    g_off[NN + 1];
__device__ int    g_bsum[SCAN_B];
__device__ int    g_bscan[SCAN_B];
__device__ int2   g_csr[NE];                // {src, float_as_int(norm)}
__device__ __half g_xw[(size_t)NN * FF];    // X @ W  (fp16)
__device__ __half g_hh[(size_t)NN * FF];    // aggregated h (fp16)
__device__ int    g_starts[GG + 1];
__device__ float  g_sum[GG * FF];
__device__ float  g_sq[GG * FF];
__device__ float  g_scale[GG * FF];
__device__ float  g_shift[GG * FF];

// helpers ---------------------------------------------------------------
__device__ __forceinline__ unsigned f2h2(float a, float b) {
    __half2 h = __floats2half2_rn(a, b);
    return *(unsigned*)&h;
}

// ============ 1. fused: init ∥ zero ∥ bounds ============
__global__ void k_pre(const int* __restrict__ batch, float* __restrict__ out_flat) {
    int blk = blockIdx.x;
    if (blk < INIT_B) {
        int i = blk * 256 + threadIdx.x;
        if (i < NN) g_pack[i] = (unsigned long long)(1u << 28);
    } else if (blk < INIT_B + ZERO_B) {
        int i = (blk - INIT_B) * 256 + threadIdx.x;
        g_sum[i] = 0.0f; g_sq[i] = 0.0f; out_flat[i] = 0.0f;
    } else {
        int i = (blk - INIT_B - ZERO_B) * 256 + threadIdx.x;
        if (i >= NN) return;
        int bv = batch[i];
        int prev = (i == 0) ? -1 : batch[i - 1];
        for (int g = prev + 1; g <= bv; ++g) g_starts[g] = i;
        if (i == NN - 1)
            for (int g = bv + 1; g <= GG; ++g) g_starts[g] = NN;
    }
}

// ============ 2. fused: deg ∥ vectorized tail ============
__global__ void k_degtail(const int* __restrict__ ei, const float* __restrict__ ew,
                          const int* __restrict__ batch, float* __restrict__ out) {
    int blk = blockIdx.x;
    if (blk < DEG_B) {
        int e = blk * 256 + threadIdx.x;
        int d = ei[NE + e];
        unsigned long long q = (unsigned long long)__float2uint_rn(ew[e] * FIXS);
        unsigned long long old = atomicAdd(&g_pack[d], (1ull << 40) | q);
        g_slot[e] = (unsigned short)(old >> 40);
    } else {
        int vt = (blk - DEG_B) * 256 + threadIdx.x;
        if (vt >= TAILV) return;
        if (vt < 800000) {                       // edge_index: 2*NE ints
            int j = vt * 4;
            int4 v = *(const int4*)(ei + j);
            float4 o = make_float4((float)v.x, (float)v.y, (float)v.z, (float)v.w);
            *(float4*)(out + OUT_EI + j) = o;
        } else if (vt < 1200000) {               // edge_weight: NE floats
            int j = (vt - 800000) * 4;
            *(float4*)(out + OUT_EW + j) = *(const float4*)(ew + j);
        } else {                                 // batch: NN ints
            int j = (vt - 1200000) * 4;
            int4 v = *(const int4*)(batch + j);
            float4 o = make_float4((float)v.x, (float)v.y, (float)v.z, (float)v.w);
            *(float4*)(out + OUT_B + j) = o;
        }
    }
}

// ============ 3. scans ============
__global__ void k_scan1() {
    __shared__ int sh[SCAN_T];
    int t = threadIdx.x;
    int base = blockIdx.x * SCAN_T * SCAN_I + t * SCAN_I;
    int s = 0;
#pragma unroll
    for (int k = 0; k < SCAN_I; ++k) {
        int i = base + k;
        if (i < NN) {
            unsigned long long p = g_pack[i];
            int c = (int)(p >> 40);
            g_cnt[i] = c;
            g_dis[i] = rsqrtf((float)(p & 0xFFFFFFFFFFull) * FIXR);
            s += c;
        }
    }
    sh[t] = s;
    __syncthreads();
    for (int off = SCAN_T / 2; off > 0; off >>= 1) {
        if (t < off) sh[t] += sh[t + off];
        __syncthreads();
    }
    if (t == 0) g_bsum[blockIdx.x] = sh[0];
}

__global__ void k_scan2() {
    __shared__ int sh[128];
    int t = threadIdx.x;
    sh[t] = (t < SCAN_B) ? g_bsum[t] : 0;
    __syncthreads();
    for (int off = 1; off < 128; off <<= 1) {
        int v = (t >= off) ? sh[t - off] : 0;
        __syncthreads();
        sh[t] += v;
        __syncthreads();
    }
    if (t < SCAN_B) g_bscan[t] = sh[t] - g_bsum[t];
}

__global__ void k_scan3() {
    __shared__ int sh[SCAN_T];
    int t = threadIdx.x;
    int base = blockIdx.x * SCAN_T * SCAN_I + t * SCAN_I;
    int c[SCAN_I];
    int s = 0;
#pragma unroll
    for (int k = 0; k < SCAN_I; ++k) {
        int i = base + k;
        c[k] = (i < NN) ? g_cnt[i] : 0;
        s += c[k];
    }
    sh[t] = s;
    __syncthreads();
    for (int off = 1; off < SCAN_T; off <<= 1) {
        int v = (t >= off) ? sh[t - off] : 0;
        __syncthreads();
        sh[t] += v;
        __syncthreads();
    }
    int run = g_bscan[blockIdx.x] + sh[t] - s;
#pragma unroll
    for (int k = 0; k < SCAN_I; ++k) {
        int i = base + k;
        if (i < NN) g_off[i] = run;
        run += c[k];
    }
    if (blockIdx.x == 0 && t == 0) g_off[NN] = NE;
}

// ============ 4. fused: HMMA gemm ∥ atomic-free csr fill ============
__global__ __launch_bounds__(256) void k_csrgemm(const float* __restrict__ X,
                                                 const float* __restrict__ W,
                                                 const int* __restrict__ ei,
                                                 const float* __restrict__ ew) {
    __shared__ __half2 Wp[64][136];
    int blk = blockIdx.x;
    int tid = threadIdx.x;

    if (blk >= GEMM_B) {
        // ---- CSR fill ----
        int e = (blk - GEMM_B) * 256 + tid;
        if (e < NE) {
            int s = ei[e];
            int d = ei[NE + e];
            float nrm = g_dis[s] * ew[e] * g_dis[d];
            int pos = g_off[d] + (int)g_slot[e];
            g_csr[pos] = make_int2(s, __float_as_int(nrm));
        }
        return;
    }

    // ---- GEMM tile ----
    int r0 = blk * 128;
    for (int idx = tid; idx < 64 * 32; idx += 256) {
        int kp = idx >> 5;
        int n4 = (idx & 31) * 4;
        float4 w0 = *(const float4*)(W + (size_t)(2 * kp) * FF + n4);
        float4 w1 = *(const float4*)(W + (size_t)(2 * kp + 1) * FF + n4);
        Wp[kp][n4 + 0] = __floats2half2_rn(w0.x, w1.x);
        Wp[kp][n4 + 1] = __floats2half2_rn(w0.y, w1.y);
        Wp[kp][n4 + 2] = __floats2half2_rn(w0.z, w1.z);
        Wp[kp][n4 + 3] = __floats2half2_rn(w0.w, w1.w);
    }
    __syncthreads();

    int warp = tid >> 5, lane = tid & 31;
    int gid = lane >> 2;
    int tig = lane & 3;
    int r_lo = r0 + warp * 16 + gid;
    int r_hi = r_lo + 8;
    bool vlo = r_lo < NN, vhi = r_hi < NN;
    const float2* plo = (const float2*)(X + (size_t)r_lo * FF);
    const float2* phi = (const float2*)(X + (size_t)r_hi * FF);
    int c2 = tig;

    float acc[16][4];
#pragma unroll
    for (int nt = 0; nt < 16; ++nt)
#pragma unroll
        for (int q = 0; q < 4; ++q) acc[nt][q] = 0.0f;

#pragma unroll
    for (int kk = 0; kk < 8; ++kk) {
        int kb = kk * 8;
        float2 z = make_float2(0.f, 0.f);
        float2 f0 = vlo ? plo[kb + c2]     : z;
        float2 f1 = vhi ? phi[kb + c2]     : z;
        float2 f2 = vlo ? plo[kb + c2 + 4] : z;
        float2 f3 = vhi ? phi[kb + c2 + 4] : z;
        unsigned a0 = f2h2(f0.x, f0.y);
        unsigned a1 = f2h2(f1.x, f1.y);
        unsigned a2 = f2h2(f2.x, f2.y);
        unsigned a3 = f2h2(f3.x, f3.y);
        int kp = kb + tig;
#pragma unroll
        for (int nt = 0; nt < 16; ++nt) {
            int n = nt * 8 + gid;
            unsigned b0 = *(unsigned*)&Wp[kp][n];
            unsigned b1 = *(unsigned*)&Wp[kp + 4][n];
            asm volatile(
                "mma.sync.aligned.m16n8k16.row.col.f32.f16.f16.f32 "
                "{%0,%1,%2,%3},{%4,%5,%6,%7},{%8,%9},{%0,%1,%2,%3};"
                : "+f"(acc[nt][0]), "+f"(acc[nt][1]), "+f"(acc[nt][2]), "+f"(acc[nt][3])
                : "r"(a0), "r"(a1), "r"(a2), "r"(a3), "r"(b0), "r"(b1));
        }
    }

#pragma unroll
    for (int nt = 0; nt < 16; ++nt) {
        int col = nt * 8 + tig * 2;
        if (vlo) {
            __half2 h = __floats2half2_rn(acc[nt][0], acc[nt][1]);
            *(__half2*)(g_xw + (size_t)r_lo * FF + col) = h;
        }
        if (vhi) {
            __half2 h = __floats2half2_rn(acc[nt][2], acc[nt][3]);
            *(__half2*)(g_xw + (size_t)r_hi * FF + col) = h;
        }
    }
}

// fp16 row fragment (4 feats) -> 4 floats
__device__ __forceinline__ float4 ld_row_h(int node, int lane) {
    uint2 r = *((const uint2*)(g_xw + (size_t)node * FF) + lane);
    __half2 h0 = *reinterpret_cast<__half2*>(&r.x);
    __half2 h1 = *reinterpret_cast<__half2*>(&r.y);
    float2 f0 = __half22float2(h0);
    float2 f1 = __half22float2(h1);
    return make_float4(f0.x, f0.y, f1.x, f1.y);
}

// ============ 5. CSR gather (no atomics), fp16 out ============
__global__ __launch_bounds__(256) void k_gather(const float* __restrict__ b) {
    int node = blockIdx.x * 8 + (threadIdx.x >> 5);
    if (node >= NN) return;
    int lane = threadIdx.x & 31;
    float dv = g_dis[node];
    float d2 = dv * dv;
    float4 x = ld_row_h(node, lane);
    float4 bb = *(const float4*)(b + lane * 4);
    float ax = bb.x + d2 * x.x;
    float ay = bb.y + d2 * x.y;
    float az = bb.z + d2 * x.z;
    float aw = bb.w + d2 * x.w;

    int j = g_off[node], j1 = g_off[node + 1];
    for (; j + 4 <= j1; j += 4) {
        int2 e0 = g_csr[j], e1 = g_csr[j + 1], e2 = g_csr[j + 2], e3 = g_csr[j + 3];
        float4 v0 = ld_row_h(e0.x, lane);
        float4 v1 = ld_row_h(e1.x, lane);
        float4 v2 = ld_row_h(e2.x, lane);
        float4 v3 = ld_row_h(e3.x, lane);
        float n0 = __int_as_float(e0.y), n1 = __int_as_float(e1.y);
        float n2 = __int_as_float(e2.y), n3 = __int_as_float(e3.y);
        ax += n0 * v0.x + n1 * v1.x + n2 * v2.x + n3 * v3.x;
        ay += n0 * v0.y + n1 * v1.y + n2 * v2.y + n3 * v3.y;
        az += n0 * v0.z + n1 * v1.z + n2 * v2.z + n3 * v3.z;
        aw += n0 * v0.w + n1 * v1.w + n2 * v2.w + n3 * v3.w;
    }
    for (; j < j1; ++j) {
        int2 e0 = g_csr[j];
        float n0 = __int_as_float(e0.y);
        float4 v0 = ld_row_h(e0.x, lane);
        ax += n0 * v0.x; ay += n0 * v0.y; az += n0 * v0.z; aw += n0 * v0.w;
    }
    uint2 pk;
    pk.x = f2h2(ax, ay);
    pk.y = f2h2(az, aw);
    *((uint2*)(g_hh + (size_t)node * FF) + lane) = pk;
}

// ============ 6. stats ============
__global__ void k_stats() {
    int g = blockIdx.y, c = blockIdx.x, f = threadIdx.x;
    int s = g_starts[g], e = g_starts[g + 1];
    int per = (e - s + gridDim.x - 1) / gridDim.x;
    int i0 = s + c * per;
    int i1 = min(i0 + per, e);
    float s1 = 0.0f, s2 = 0.0f;
    for (int i = i0; i < i1; ++i) {
        float v = __half2float(g_hh[(size_t)i * FF + f]);
        s1 += v; s2 += v * v;
    }
    if (i1 > i0) {
        atomicAdd(&g_sum[g * FF + f], s1);
        atomicAdd(&g_sq[g * FF + f], s2);
    }
}

// ============ 7. affine fold ============
__global__ void k_affine(const float* __restrict__ ms, const float* __restrict__ gnw,
                         const float* __restrict__ gnb) {
    int idx = blockIdx.x * blockDim.x + threadIdx.x;
    if (idx >= GG * FF) return;
    int g = idx >> 7, f = idx & 127;
    float cnt = fmaxf((float)(g_starts[g + 1] - g_starts[g]), 1.0f);
    float mean = g_sum[idx] / cnt;
    float m2 = mean * ms[f];
    float var = g_sq[idx] / cnt - 2.0f * m2 * mean + m2 * m2;
    var = fmaxf(var, 0.0f);
    float rstd = rsqrtf(var + EPSV);
    float sc = gnw[f] * rstd;
    g_scale[idx] = sc;
    g_shift[idx] = gnb[f] - sc * m2;
}

// ============ 8. normalize + ReLU + h_emb + per-graph max ============
__global__ void k_final(float* __restrict__ out_h, float* __restrict__ out_flat) {
    int g = blockIdx.y, c = blockIdx.x, f = threadIdx.x;
    int s = g_starts[g], e = g_starts[g + 1];
    int per = (e - s + gridDim.x - 1) / gridDim.x;
    int i0 = s + c * per;
    int i1 = min(i0 + per, e);
    float sc = g_scale[g * FF + f];
    float sh = g_shift[g * FF + f];
    float m = 0.0f;
    for (int i = i0; i < i1; ++i) {
        float hv = __half2float(g_hh[(size_t)i * FF + f]);
        float v = fmaxf(fmaf(hv, sc, sh), 0.0f);
        out_h[(size_t)i * FF + f] = v;
        m = fmaxf(m, v);
    }
    if (i1 > i0) atomicMax((int*)&out_flat[g * FF + f], __float_as_int(m));
}

// ---------------------------------------------------------------------------
extern "C" void kernel_launch(void* const* d_in, const int* in_sizes, int n_in,
                              void* d_out, int out_size) {
    const float* X   = (const float*)d_in[0];
    const int*   ei  = (const int*)d_in[1];
    const int*   bat = (const int*)d_in[2];
    const float* ew  = (const float*)d_in[3];
    const float* W   = (const float*)d_in[4];
    const float* b   = (const float*)d_in[5];
    const float* gnw = (const float*)d_in[6];
    const float* gnb = (const float*)d_in[7];
    const float* gms = (const float*)d_in[8];
    float* out = (float*)d_out;

    k_pre<<<INIT_B + ZERO_B + BOUNDS_B, 256>>>(bat, out + OUT_FLAT);
    k_degtail<<<DEG_B + TAIL_B, 256>>>(ei, ew, bat, out);

    k_scan1<<<SCAN_B, SCAN_T>>>();
    k_scan2<<<1, 128>>>();
    k_scan3<<<SCAN_B, SCAN_T>>>();

    k_csrgemm<<<GEMM_B + CSR_B, 256>>>(X, W, ei, ew);

    k_gather<<<(NN + 7) / 8, 256>>>(b);

    dim3 sgrid(16, GG);
    k_stats<<<sgrid, FF>>>();
    k_affine<<<(GG * FF + 255) / 256, 256>>>(gms, gnw, gnb);

    dim3 fgrid(32, GG);
    k_final<<<fgrid, FF>>>(out, out + OUT_FLAT);
}